// round 2
// baseline (speedup 1.0000x reference)
#include <cuda_runtime.h>
#include <math.h>

#define NTOK 4096   // B*T
#define DM   1024
#define NH   16
#define DH   64
#define TT   2048
#define BB   2
#define APAD 68

// Scratch (allocation-free rule: __device__ globals)
__device__ float g_Q[NTOK*DM];
__device__ float g_K[NTOK*DM];
__device__ float g_V[NTOK*DM];
__device__ float g_G[NTOK*DM];
__device__ float g_R[NTOK*DM];
__device__ float g_Y[NTOK*DM];

// ---------------------------------------------------------------------------
// SGEMM: C[M,N] = A[M,K] @ B[K,N] (+bias) (optional swish). 128x128x8 tile,
// 256 threads, 8x8 per thread.
// ---------------------------------------------------------------------------
template<int ACT>
__global__ __launch_bounds__(256) void sgemm_kernel(
    const float* __restrict__ A, const float* __restrict__ B,
    const float* __restrict__ bias, float* __restrict__ C,
    int M, int N, int K)
{
    __shared__ float As[8][132];   // transposed: As[k][m]
    __shared__ float Bs[8][128];   // natural:    Bs[k][n]

    const int m0 = blockIdx.y * 128;
    const int n0 = blockIdx.x * 128;
    const int t  = threadIdx.x;
    const int tx = t & 15, ty = t >> 4;

    const int arow = t >> 1;
    const int aseg = (t & 1) * 4;
    const int brow = t >> 5;
    const int bcol = (t & 31) * 4;

    float acc[8][8];
    #pragma unroll
    for (int i = 0; i < 8; i++)
        #pragma unroll
        for (int j = 0; j < 8; j++) acc[i][j] = 0.f;

    for (int k0 = 0; k0 < K; k0 += 8) {
        float4 av = *(const float4*)(A + (size_t)(m0 + arow) * K + k0 + aseg);
        float4 bv = *(const float4*)(B + (size_t)(k0 + brow) * N + n0 + bcol);
        __syncthreads();
        As[aseg + 0][arow] = av.x;
        As[aseg + 1][arow] = av.y;
        As[aseg + 2][arow] = av.z;
        As[aseg + 3][arow] = av.w;
        *(float4*)&Bs[brow][bcol] = bv;
        __syncthreads();

        #pragma unroll
        for (int k = 0; k < 8; k++) {
            float a[8], b[8];
            *(float4*)&a[0] = *(const float4*)&As[k][ty * 8];
            *(float4*)&a[4] = *(const float4*)&As[k][ty * 8 + 4];
            *(float4*)&b[0] = *(const float4*)&Bs[k][tx * 8];
            *(float4*)&b[4] = *(const float4*)&Bs[k][tx * 8 + 4];
            #pragma unroll
            for (int i = 0; i < 8; i++)
                #pragma unroll
                for (int j = 0; j < 8; j++)
                    acc[i][j] += a[i] * b[j];
        }
    }

    float bs[8];
    if (bias) {
        *(float4*)&bs[0] = *(const float4*)(bias + n0 + tx * 8);
        *(float4*)&bs[4] = *(const float4*)(bias + n0 + tx * 8 + 4);
    } else {
        #pragma unroll
        for (int j = 0; j < 8; j++) bs[j] = 0.f;
    }

    #pragma unroll
    for (int i = 0; i < 8; i++) {
        int m = m0 + ty * 8 + i;
        float out[8];
        #pragma unroll
        for (int j = 0; j < 8; j++) {
            float z = acc[i][j] + bs[j];
            if (ACT == 1) z = z / (1.0f + expf(-z));   // swish
            out[j] = z;
        }
        *(float4*)(C + (size_t)m * N + n0 + tx * 8)     = *(float4*)&out[0];
        *(float4*)(C + (size_t)m * N + n0 + tx * 8 + 4) = *(float4*)&out[4];
    }
}

// ---------------------------------------------------------------------------
// Retention: R = (Q K^T / 8 * decay_mask) @ V, tiled 64x64 per head/block.
// Decay factored: gamma^(diff) = gamma^r * gamma^-c * gamma^(64*dblock).
// Per-head window: skip blocks where decay < 2^-24.
// ---------------------------------------------------------------------------
__global__ __launch_bounds__(256) void retention_kernel(
    const float* __restrict__ Q, const float* __restrict__ K,
    const float* __restrict__ V, float* __restrict__ R)
{
    extern __shared__ float sm[];
    float* Qt = sm;                 // [64][APAD] d-major (transposed)
    float* Kt = sm + 64 * APAD;     // [64][APAD] d-major
    float* Vs = sm + 2 * 64 * APAD; // [64][APAD] s-major (natural)
    float* Ss = sm + 3 * 64 * APAD; // [64][APAD] scores

    const int qb = blockIdx.x, h = blockIdx.y, b = blockIdx.z;
    const int t  = threadIdx.x;
    const int tx = t & 15, ty = t >> 4;
    const int r0 = ty * 4, c0 = tx * 4;

    const size_t base = (size_t)b * TT * DM + (size_t)h * DH;
    const int t0 = qb * 64;

    // Load Q tile transposed
    #pragma unroll
    for (int i = 0; i < 4; i++) {
        int f = t + i * 256;
        int row = f >> 4;
        int d0 = (f & 15) * 4;
        float4 v = *(const float4*)(Q + base + (size_t)(t0 + row) * DM + d0);
        Qt[(d0 + 0) * APAD + row] = v.x;
        Qt[(d0 + 1) * APAD + row] = v.y;
        Qt[(d0 + 2) * APAD + row] = v.z;
        Qt[(d0 + 3) * APAD + row] = v.w;
    }

    const float gamma = 1.0f - exp2f(-(float)(5 + h));
    const float l2g   = log2f(gamma);            // negative
    float diffmax = 24.0f / (-l2g);
    int nb_back = (diffmax > 1.0e8f) ? qb : ((int)(diffmax * (1.0f / 64.0f)) + 2);
    int sb0 = qb - nb_back; if (sb0 < 0) sb0 = 0;

    float pr[4], pc[4];
    #pragma unroll
    for (int i = 0; i < 4; i++) {
        pr[i] = exp2f(l2g * (float)(r0 + i)) * 0.125f;  // fold 1/sqrt(dh)
        pc[i] = exp2f(-l2g * (float)(c0 + i));
    }

    float o[4][4];
    #pragma unroll
    for (int i = 0; i < 4; i++)
        #pragma unroll
        for (int j = 0; j < 4; j++) o[i][j] = 0.f;

    for (int sb = sb0; sb <= qb; sb++) {
        const int s0t = sb * 64;
        // Load K (transposed) and V (natural)
        #pragma unroll
        for (int i = 0; i < 4; i++) {
            int f = t + i * 256;
            int row = f >> 4;
            int d0 = (f & 15) * 4;
            float4 kv = *(const float4*)(K + base + (size_t)(s0t + row) * DM + d0);
            float4 vv = *(const float4*)(V + base + (size_t)(s0t + row) * DM + d0);
            Kt[(d0 + 0) * APAD + row] = kv.x;
            Kt[(d0 + 1) * APAD + row] = kv.y;
            Kt[(d0 + 2) * APAD + row] = kv.z;
            Kt[(d0 + 3) * APAD + row] = kv.w;
            *(float4*)&Vs[row * APAD + d0] = vv;
        }
        __syncthreads();

        // Stage 1: S = Q K^T
        float s[4][4];
        #pragma unroll
        for (int i = 0; i < 4; i++)
            #pragma unroll
            for (int j = 0; j < 4; j++) s[i][j] = 0.f;

        #pragma unroll 16
        for (int d = 0; d < 64; d++) {
            float4 q  = *(const float4*)&Qt[d * APAD + r0];
            float4 kk = *(const float4*)&Kt[d * APAD + c0];
            float qa[4] = {q.x, q.y, q.z, q.w};
            float ka[4] = {kk.x, kk.y, kk.z, kk.w};
            #pragma unroll
            for (int i = 0; i < 4; i++)
                #pragma unroll
                for (int j = 0; j < 4; j++)
                    s[i][j] += qa[i] * ka[j];
        }

        const float pb = exp2f(l2g * (float)(64 * (qb - sb)));
        const bool diag = (sb == qb);
        #pragma unroll
        for (int i = 0; i < 4; i++) {
            #pragma unroll
            for (int j = 0; j < 4; j++) {
                float w = pr[i] * pc[j] * pb;
                float val = s[i][j] * w;
                if (diag && (c0 + j) > (r0 + i)) val = 0.f;
                Ss[(r0 + i) * APAD + c0 + j] = val;
            }
        }
        __syncthreads();

        // Stage 2: O += S @ V
        #pragma unroll 8
        for (int ss = 0; ss < 64; ss++) {
            float a0 = Ss[(r0 + 0) * APAD + ss];
            float a1 = Ss[(r0 + 1) * APAD + ss];
            float a2 = Ss[(r0 + 2) * APAD + ss];
            float a3 = Ss[(r0 + 3) * APAD + ss];
            float4 v = *(const float4*)&Vs[ss * APAD + c0];
            o[0][0] += a0 * v.x; o[0][1] += a0 * v.y; o[0][2] += a0 * v.z; o[0][3] += a0 * v.w;
            o[1][0] += a1 * v.x; o[1][1] += a1 * v.y; o[1][2] += a1 * v.z; o[1][3] += a1 * v.w;
            o[2][0] += a2 * v.x; o[2][1] += a2 * v.y; o[2][2] += a2 * v.z; o[2][3] += a2 * v.w;
            o[3][0] += a3 * v.x; o[3][1] += a3 * v.y; o[3][2] += a3 * v.z; o[3][3] += a3 * v.w;
        }
        __syncthreads();
    }

    // Write [B,T,H,dh] == [B,T,D] head-concat layout
    #pragma unroll
    for (int i = 0; i < 4; i++) {
        float4 v = make_float4(o[i][0], o[i][1], o[i][2], o[i][3]);
        *(float4*)(R + base + (size_t)(t0 + r0 + i) * DM + c0) = v;
    }
}

// ---------------------------------------------------------------------------
// LayerNorm(row) * gate, one block per token row of 1024
// ---------------------------------------------------------------------------
__global__ __launch_bounds__(256) void ln_gate_kernel(
    const float* __restrict__ R, const float* __restrict__ G,
    const float* __restrict__ lng, const float* __restrict__ lnb,
    float* __restrict__ Y)
{
    __shared__ float red[8];
    const int row = blockIdx.x;
    const int t = threadIdx.x;
    const size_t off = (size_t)row * DM + t * 4;

    float4 x = *(const float4*)(R + off);

    float s = x.x + x.y + x.z + x.w;
    #pragma unroll
    for (int o = 16; o > 0; o >>= 1) s += __shfl_xor_sync(0xffffffffu, s, o);
    if ((t & 31) == 0) red[t >> 5] = s;
    __syncthreads();
    float tot = red[0] + red[1] + red[2] + red[3] + red[4] + red[5] + red[6] + red[7];
    const float mu = tot * (1.0f / 1024.0f);

    float d0 = x.x - mu, d1 = x.y - mu, d2 = x.z - mu, d3 = x.w - mu;
    float sq = d0 * d0 + d1 * d1 + d2 * d2 + d3 * d3;
    #pragma unroll
    for (int o = 16; o > 0; o >>= 1) sq += __shfl_xor_sync(0xffffffffu, sq, o);
    __syncthreads();                       // done reading red
    if ((t & 31) == 0) red[t >> 5] = sq;
    __syncthreads();
    float totsq = red[0] + red[1] + red[2] + red[3] + red[4] + red[5] + red[6] + red[7];
    const float rstd = rsqrtf(totsq * (1.0f / 1024.0f) + 1e-3f);

    float4 g4 = *(const float4*)(lng + t * 4);
    float4 b4 = *(const float4*)(lnb + t * 4);
    float4 gt = *(const float4*)(G + off);

    float4 y;
    y.x = (d0 * rstd * g4.x + b4.x) * gt.x;
    y.y = (d1 * rstd * g4.y + b4.y) * gt.y;
    y.z = (d2 * rstd * g4.z + b4.z) * gt.z;
    y.w = (d3 * rstd * g4.w + b4.w) * gt.w;
    *(float4*)(Y + off) = y;
}

// ---------------------------------------------------------------------------
extern "C" void kernel_launch(void* const* d_in, const int* in_sizes, int n_in,
                              void* d_out, int out_size)
{
    const float* x   = (const float*)d_in[0];
    const float* Wq  = (const float*)d_in[1];
    const float* Wk  = (const float*)d_in[2];
    const float* Wv  = (const float*)d_in[3];
    const float* Wg  = (const float*)d_in[4];
    const float* bg  = (const float*)d_in[5];
    const float* Wo  = (const float*)d_in[6];
    const float* bo  = (const float*)d_in[7];
    const float* lng = (const float*)d_in[8];
    const float* lnb = (const float*)d_in[9];

    float *Q, *K, *V, *G, *R, *Y;
    cudaGetSymbolAddress((void**)&Q, g_Q);
    cudaGetSymbolAddress((void**)&K, g_K);
    cudaGetSymbolAddress((void**)&V, g_V);
    cudaGetSymbolAddress((void**)&G, g_G);
    cudaGetSymbolAddress((void**)&R, g_R);
    cudaGetSymbolAddress((void**)&Y, g_Y);

    dim3 gg(DM / 128, NTOK / 128);  // (8, 32)
    sgemm_kernel<0><<<gg, 256>>>(x, Wq, nullptr, Q, NTOK, DM, DM);
    sgemm_kernel<0><<<gg, 256>>>(x, Wk, nullptr, K, NTOK, DM, DM);
    sgemm_kernel<0><<<gg, 256>>>(x, Wv, nullptr, V, NTOK, DM, DM);
    sgemm_kernel<1><<<gg, 256>>>(x, Wg, bg,      G, NTOK, DM, DM);

    const int smem = 4 * 64 * APAD * sizeof(float);  // 69632 B
    cudaFuncSetAttribute(retention_kernel,
                         cudaFuncAttributeMaxDynamicSharedMemorySize, smem);
    retention_kernel<<<dim3(TT / 64, NH, BB), 256, smem>>>(Q, K, V, R);

    ln_gate_kernel<<<NTOK, 256>>>(R, G, lng, lnb, Y);

    sgemm_kernel<0><<<gg, 256>>>(Y, Wo, bo, (float*)d_out, NTOK, DM, DM);
}

// round 6
// speedup vs baseline: 1.7120x; 1.7120x over previous
#include <cuda_runtime.h>
#include <math.h>
#include <stdint.h>

#define NTOK 4096   // B*T
#define DM   1024
#define NH   16
#define DH   64
#define TT   2048
#define BB   2
#define APAD 68

#define KT      32          // k-tile
#define NKT     (DM/KT)     // 32
#define LDS_S   36          // padded k-stride in smem (floats)
#define TILE_FL (128*LDS_S) // floats per operand buffer
#define GEMM_SMEM (2*2*TILE_FL*4)  // 2 buffers x (A+B) = 73728 B

// Scratch (__device__ globals: allocation-free rule)
__device__ float g_Q[NTOK*DM];
__device__ float g_K[NTOK*DM];
__device__ float g_V[NTOK*DM];
__device__ float g_G[NTOK*DM];
__device__ float g_R[NTOK*DM];
__device__ float g_Y[NTOK*DM];
__device__ float g_Xr[NTOK*DM];
__device__ float g_Wt4[4*DM*DM];
__device__ float g_Wot[DM*DM];

__device__ __forceinline__ uint32_t smem_u32(const void* p) {
    uint32_t a;
    asm("{ .reg .u64 t; cvta.to.shared.u64 t, %1; cvt.u32.u64 %0, t; }" : "=r"(a) : "l"(p));
    return a;
}
__device__ __forceinline__ float tf32r(float x) {
    uint32_t u; asm("cvt.rna.tf32.f32 %0, %1;" : "=r"(u) : "f"(x));
    return __uint_as_float(u);
}
__device__ __forceinline__ void cpa16(uint32_t dst, const void* src) {
    asm volatile("cp.async.cg.shared.global [%0], [%1], 16;" :: "r"(dst), "l"(src) : "memory");
}
__device__ __forceinline__ void mma_tf32(float* c, const uint32_t* a, const uint32_t* b) {
    asm volatile(
        "mma.sync.aligned.m16n8k8.row.col.f32.tf32.tf32.f32 "
        "{%0,%1,%2,%3}, {%4,%5,%6,%7}, {%8,%9}, {%0,%1,%2,%3};"
        : "+f"(c[0]), "+f"(c[1]), "+f"(c[2]), "+f"(c[3])
        : "r"(a[0]), "r"(a[1]), "r"(a[2]), "r"(a[3]), "r"(b[0]), "r"(b[1]));
}

struct GemmCfg {
    float* out[4];
    const float* bias[4];
    int act[4];
};

// ---------------------------------------------------------------------------
// tf32 mma.sync GEMM: C tile 128x128 = A[M,1024] @ Bt[N,1024]^T
// 256 threads = 8 warps (2 x 4); each warp 64x32 via m16n8k8 MMAs.
// ---------------------------------------------------------------------------
__global__ __launch_bounds__(256) void gemm_tc(
    const float* __restrict__ A, const float* __restrict__ Bt, GemmCfg cfg)
{
    extern __shared__ __align__(16) float smem[];
    float* As[2] = { smem,                smem + 2*TILE_FL };
    float* Bs[2] = { smem + TILE_FL,      smem + 3*TILE_FL };

    const int t = threadIdx.x;
    const int wid = t >> 5, lane = t & 31;
    const int wm = wid >> 2, wn = wid & 3;         // 2 x 4 warp grid
    const int m0 = blockIdx.y * 128, n0 = blockIdx.x * 128;
    const int bsel = n0 >> 10;
    const int ncol0 = n0 & 1023;

    const int lq = lane >> 2;       // 0..7
    const int lr = lane & 3;        // 0..3

    // cp.async segment mapping: 1024 float4 per operand, 4 per thread
    // seg s: row = s>>3, col4 = s&7
    const uint32_t sA0 = smem_u32(As[0]);
    const uint32_t sB0 = smem_u32(Bs[0]);
    const uint32_t bufStride = 2*TILE_FL*4;  // bytes between buffers

    float acc[4][4][4];
    #pragma unroll
    for (int i = 0; i < 4; i++)
        #pragma unroll
        for (int j = 0; j < 4; j++)
            #pragma unroll
            for (int q = 0; q < 4; q++) acc[i][j][q] = 0.f;

    auto loadTile = [&](int kt, int buf) {
        const int k0 = kt * KT;
        #pragma unroll
        for (int i = 0; i < 4; i++) {
            int s = t + i * 256;
            int row = s >> 3, c4 = (s & 7) * 4;
            cpa16(sA0 + buf * bufStride + (row * LDS_S + c4) * 4,
                  A + (size_t)(m0 + row) * DM + k0 + c4);
            cpa16(sB0 + buf * bufStride + (row * LDS_S + c4) * 4,
                  Bt + (size_t)(n0 + row) * DM + k0 + c4);
        }
        asm volatile("cp.async.commit_group;" ::: "memory");
    };

    loadTile(0, 0);

    for (int kt = 0; kt < NKT; kt++) {
        if (kt + 1 < NKT) {
            loadTile(kt + 1, (kt + 1) & 1);
            asm volatile("cp.async.wait_group 1;" ::: "memory");
        } else {
            asm volatile("cp.async.wait_group 0;" ::: "memory");
        }
        __syncthreads();

        const float* a_s = As[kt & 1];
        const float* b_s = Bs[kt & 1];

        #pragma unroll
        for (int ks = 0; ks < KT / 8; ks++) {
            const int k0 = ks * 8;
            uint32_t af[4][4], bf[4][2];
            #pragma unroll
            for (int mi = 0; mi < 4; mi++) {
                const float* ap = a_s + (wm * 64 + mi * 16 + lq) * LDS_S + k0 + lr;
                af[mi][0] = __float_as_uint(ap[0]);
                af[mi][1] = __float_as_uint(ap[8 * LDS_S]);
                af[mi][2] = __float_as_uint(ap[4]);
                af[mi][3] = __float_as_uint(ap[8 * LDS_S + 4]);
            }
            #pragma unroll
            for (int ni = 0; ni < 4; ni++) {
                const float* bp = b_s + (wn * 32 + ni * 8 + lq) * LDS_S + k0 + lr;
                bf[ni][0] = __float_as_uint(bp[0]);
                bf[ni][1] = __float_as_uint(bp[4]);
            }
            #pragma unroll
            for (int mi = 0; mi < 4; mi++)
                #pragma unroll
                for (int ni = 0; ni < 4; ni++)
                    mma_tf32(acc[mi][ni], af[mi], bf[ni]);
        }
        __syncthreads();
    }

    // Epilogue: bias + optional swish, direct stores
    float* outp = cfg.out[bsel];
    const float* bp = cfg.bias[bsel];
    const int act = cfg.act[bsel];

    #pragma unroll
    for (int mi = 0; mi < 4; mi++) {
        #pragma unroll
        for (int ni = 0; ni < 4; ni++) {
            const int col = ncol0 + wn * 32 + ni * 8 + lr * 2;
            float b0 = 0.f, b1 = 0.f;
            if (bp) { b0 = bp[col]; b1 = bp[col + 1]; }
            #pragma unroll
            for (int h = 0; h < 2; h++) {
                const int row = m0 + wm * 64 + mi * 16 + lq + h * 8;
                float z0 = acc[mi][ni][h * 2 + 0] + b0;
                float z1 = acc[mi][ni][h * 2 + 1] + b1;
                if (act) {
                    z0 = z0 / (1.0f + expf(-z0));
                    z1 = z1 / (1.0f + expf(-z1));
                }
                float2 v = make_float2(z0, z1);
                *(float2*)(outp + (size_t)row * DM + col) = v;
            }
        }
    }
}

// ---------------------------------------------------------------------------
// Prep kernels: tf32 rounding + weight transpose
// ---------------------------------------------------------------------------
__global__ __launch_bounds__(256) void round_copy(const float* __restrict__ in,
                                                  float* __restrict__ out)
{
    size_t i = ((size_t)blockIdx.x * 256 + threadIdx.x) * 4;
    float4 v = *(const float4*)(in + i);
    v.x = tf32r(v.x); v.y = tf32r(v.y); v.z = tf32r(v.z); v.w = tf32r(v.w);
    *(float4*)(out + i) = v;
}

__global__ __launch_bounds__(256) void transpose_round(const float* __restrict__ W,
                                                       float* __restrict__ Wt)
{
    __shared__ float tile[32][33];
    const int k0 = blockIdx.x * 32, n0 = blockIdx.y * 32;
    const int tx = threadIdx.x & 31, ty = threadIdx.x >> 5;  // 32x8
    #pragma unroll
    for (int i = 0; i < 32; i += 8)
        tile[ty + i][tx] = W[(size_t)(k0 + ty + i) * DM + n0 + tx];
    __syncthreads();
    #pragma unroll
    for (int i = 0; i < 32; i += 8)
        Wt[(size_t)(n0 + ty + i) * DM + k0 + tx] = tf32r(tile[tx][ty + i]);
}

// ---------------------------------------------------------------------------
// Retention (SIMT): R = (Q K^T / 8 * decay) @ V, 64x64 tiles
// ---------------------------------------------------------------------------
__global__ __launch_bounds__(256) void retention_kernel(
    const float* __restrict__ Q, const float* __restrict__ K,
    const float* __restrict__ V, float* __restrict__ R)
{
    extern __shared__ float sm[];
    float* Qt = sm;
    float* Kt = sm + 64 * APAD;
    float* Vs = sm + 2 * 64 * APAD;
    float* Ss = sm + 3 * 64 * APAD;

    const int qb = blockIdx.x, h = blockIdx.y, b = blockIdx.z;
    const int t  = threadIdx.x;
    const int tx = t & 15, ty = t >> 4;
    const int r0 = ty * 4, c0 = tx * 4;

    const size_t base = (size_t)b * TT * DM + (size_t)h * DH;
    const int t0 = qb * 64;

    #pragma unroll
    for (int i = 0; i < 4; i++) {
        int f = t + i * 256;
        int row = f >> 4;
        int d0 = (f & 15) * 4;
        float4 v = *(const float4*)(Q + base + (size_t)(t0 + row) * DM + d0);
        Qt[(d0 + 0) * APAD + row] = v.x;
        Qt[(d0 + 1) * APAD + row] = v.y;
        Qt[(d0 + 2) * APAD + row] = v.z;
        Qt[(d0 + 3) * APAD + row] = v.w;
    }

    const float gamma = 1.0f - exp2f(-(float)(5 + h));
    const float l2g   = log2f(gamma);
    float diffmax = 24.0f / (-l2g);
    int nb_back = (diffmax > 1.0e8f) ? qb : ((int)(diffmax * (1.0f / 64.0f)) + 2);
    int sb0 = qb - nb_back; if (sb0 < 0) sb0 = 0;

    float pr[4], pc[4];
    #pragma unroll
    for (int i = 0; i < 4; i++) {
        pr[i] = exp2f(l2g * (float)(r0 + i)) * 0.125f;
        pc[i] = exp2f(-l2g * (float)(c0 + i));
    }

    float o[4][4];
    #pragma unroll
    for (int i = 0; i < 4; i++)
        #pragma unroll
        for (int j = 0; j < 4; j++) o[i][j] = 0.f;

    for (int sb = sb0; sb <= qb; sb++) {
        const int s0t = sb * 64;
        #pragma unroll
        for (int i = 0; i < 4; i++) {
            int f = t + i * 256;
            int row = f >> 4;
            int d0 = (f & 15) * 4;
            float4 kv = *(const float4*)(K + base + (size_t)(s0t + row) * DM + d0);
            float4 vv = *(const float4*)(V + base + (size_t)(s0t + row) * DM + d0);
            Kt[(d0 + 0) * APAD + row] = kv.x;
            Kt[(d0 + 1) * APAD + row] = kv.y;
            Kt[(d0 + 2) * APAD + row] = kv.z;
            Kt[(d0 + 3) * APAD + row] = kv.w;
            *(float4*)&Vs[row * APAD + d0] = vv;
        }
        __syncthreads();

        float s[4][4];
        #pragma unroll
        for (int i = 0; i < 4; i++)
            #pragma unroll
            for (int j = 0; j < 4; j++) s[i][j] = 0.f;

        #pragma unroll 16
        for (int d = 0; d < 64; d++) {
            float4 q  = *(const float4*)&Qt[d * APAD + r0];
            float4 kk = *(const float4*)&Kt[d * APAD + c0];
            float qa[4] = {q.x, q.y, q.z, q.w};
            float ka[4] = {kk.x, kk.y, kk.z, kk.w};
            #pragma unroll
            for (int i = 0; i < 4; i++)
                #pragma unroll
                for (int j = 0; j < 4; j++)
                    s[i][j] += qa[i] * ka[j];
        }

        const float pb = exp2f(l2g * (float)(64 * (qb - sb)));
        const bool diag = (sb == qb);
        #pragma unroll
        for (int i = 0; i < 4; i++) {
            #pragma unroll
            for (int j = 0; j < 4; j++) {
                float w = pr[i] * pc[j] * pb;
                float val = s[i][j] * w;
                if (diag && (c0 + j) > (r0 + i)) val = 0.f;
                Ss[(r0 + i) * APAD + c0 + j] = val;
            }
        }
        __syncthreads();

        #pragma unroll 8
        for (int ss = 0; ss < 64; ss++) {
            float a0 = Ss[(r0 + 0) * APAD + ss];
            float a1 = Ss[(r0 + 1) * APAD + ss];
            float a2 = Ss[(r0 + 2) * APAD + ss];
            float a3 = Ss[(r0 + 3) * APAD + ss];
            float4 v = *(const float4*)&Vs[ss * APAD + c0];
            o[0][0] += a0 * v.x; o[0][1] += a0 * v.y; o[0][2] += a0 * v.z; o[0][3] += a0 * v.w;
            o[1][0] += a1 * v.x; o[1][1] += a1 * v.y; o[1][2] += a1 * v.z; o[1][3] += a1 * v.w;
            o[2][0] += a2 * v.x; o[2][1] += a2 * v.y; o[2][2] += a2 * v.z; o[2][3] += a2 * v.w;
            o[3][0] += a3 * v.x; o[3][1] += a3 * v.y; o[3][2] += a3 * v.z; o[3][3] += a3 * v.w;
        }
        __syncthreads();
    }

    #pragma unroll
    for (int i = 0; i < 4; i++) {
        float4 v = make_float4(o[i][0], o[i][1], o[i][2], o[i][3]);
        *(float4*)(R + base + (size_t)(t0 + r0 + i) * DM + c0) = v;
    }
}

// ---------------------------------------------------------------------------
// LayerNorm * gate (tf32-rounds Y for the tensor-core output GEMM)
// ---------------------------------------------------------------------------
__global__ __launch_bounds__(256) void ln_gate_kernel(
    const float* __restrict__ R, const float* __restrict__ G,
    const float* __restrict__ lng, const float* __restrict__ lnb,
    float* __restrict__ Y)
{
    __shared__ float red[8];
    const int row = blockIdx.x;
    const int t = threadIdx.x;
    const size_t off = (size_t)row * DM + t * 4;

    float4 x = *(const float4*)(R + off);

    float s = x.x + x.y + x.z + x.w;
    #pragma unroll
    for (int o = 16; o > 0; o >>= 1) s += __shfl_xor_sync(0xffffffffu, s, o);
    if ((t & 31) == 0) red[t >> 5] = s;
    __syncthreads();
    float tot = red[0] + red[1] + red[2] + red[3] + red[4] + red[5] + red[6] + red[7];
    const float mu = tot * (1.0f / 1024.0f);

    float d0 = x.x - mu, d1 = x.y - mu, d2 = x.z - mu, d3 = x.w - mu;
    float sq = d0 * d0 + d1 * d1 + d2 * d2 + d3 * d3;
    #pragma unroll
    for (int o = 16; o > 0; o >>= 1) sq += __shfl_xor_sync(0xffffffffu, sq, o);
    __syncthreads();
    if ((t & 31) == 0) red[t >> 5] = sq;
    __syncthreads();
    float totsq = red[0] + red[1] + red[2] + red[3] + red[4] + red[5] + red[6] + red[7];
    const float rstd = rsqrtf(totsq * (1.0f / 1024.0f) + 1e-3f);

    float4 g4 = *(const float4*)(lng + t * 4);
    float4 b4 = *(const float4*)(lnb + t * 4);
    float4 gt = *(const float4*)(G + off);

    float4 y;
    y.x = tf32r((d0 * rstd * g4.x + b4.x) * gt.x);
    y.y = tf32r((d1 * rstd * g4.y + b4.y) * gt.y);
    y.z = tf32r((d2 * rstd * g4.z + b4.z) * gt.z);
    y.w = tf32r((d3 * rstd * g4.w + b4.w) * gt.w);
    *(float4*)(Y + off) = y;
}

// ---------------------------------------------------------------------------
extern "C" void kernel_launch(void* const* d_in, const int* in_sizes, int n_in,
                              void* d_out, int out_size)
{
    const float* x   = (const float*)d_in[0];
    const float* Wq  = (const float*)d_in[1];
    const float* Wk  = (const float*)d_in[2];
    const float* Wv  = (const float*)d_in[3];
    const float* Wg  = (const float*)d_in[4];
    const float* bg  = (const float*)d_in[5];
    const float* Wo  = (const float*)d_in[6];
    const float* bo  = (const float*)d_in[7];
    const float* lng = (const float*)d_in[8];
    const float* lnb = (const float*)d_in[9];

    float *Q, *K, *V, *G, *R, *Y, *Xr, *Wt4, *Wot;
    cudaGetSymbolAddress((void**)&Q,  g_Q);
    cudaGetSymbolAddress((void**)&K,  g_K);
    cudaGetSymbolAddress((void**)&V,  g_V);
    cudaGetSymbolAddress((void**)&G,  g_G);
    cudaGetSymbolAddress((void**)&R,  g_R);
    cudaGetSymbolAddress((void**)&Y,  g_Y);
    cudaGetSymbolAddress((void**)&Xr, g_Xr);
    cudaGetSymbolAddress((void**)&Wt4, g_Wt4);
    cudaGetSymbolAddress((void**)&Wot, g_Wot);

    // Prep: tf32 rounding + weight transposes
    round_copy<<<(NTOK * DM) / (256 * 4), 256>>>(x, Xr);
    dim3 tb(256), tg(32, 32);
    transpose_round<<<tg, tb>>>(Wq, Wt4 + 0 * DM * DM);
    transpose_round<<<tg, tb>>>(Wk, Wt4 + 1 * DM * DM);
    transpose_round<<<tg, tb>>>(Wv, Wt4 + 2 * DM * DM);
    transpose_round<<<tg, tb>>>(Wg, Wt4 + 3 * DM * DM);
    transpose_round<<<tg, tb>>>(Wo, Wot);

    cudaFuncSetAttribute(gemm_tc, cudaFuncAttributeMaxDynamicSharedMemorySize, GEMM_SMEM);

    // Fused QKVG projection: N = 4096
    GemmCfg c1;
    c1.out[0] = Q;  c1.out[1] = K;  c1.out[2] = V;  c1.out[3] = G;
    c1.bias[0] = nullptr; c1.bias[1] = nullptr; c1.bias[2] = nullptr; c1.bias[3] = bg;
    c1.act[0] = 0; c1.act[1] = 0; c1.act[2] = 0; c1.act[3] = 1;
    gemm_tc<<<dim3(32, 32), 256, GEMM_SMEM>>>(Xr, Wt4, c1);

    const int smem = 4 * 64 * APAD * sizeof(float);
    cudaFuncSetAttribute(retention_kernel,
                         cudaFuncAttributeMaxDynamicSharedMemorySize, smem);
    retention_kernel<<<dim3(TT / 64, NH, BB), 256, smem>>>(Q, K, V, R);

    ln_gate_kernel<<<NTOK, 256>>>(R, G, lng, lnb, Y);

    // Output projection
    GemmCfg c2;
    c2.out[0] = (float*)d_out; c2.out[1] = nullptr; c2.out[2] = nullptr; c2.out[3] = nullptr;
    c2.bias[0] = bo; c2.bias[1] = nullptr; c2.bias[2] = nullptr; c2.bias[3] = nullptr;
    c2.act[0] = 0; c2.act[1] = 0; c2.act[2] = 0; c2.act[3] = 0;
    gemm_tc<<<dim3(8, 32), 256, GEMM_SMEM>>>(Y, Wot, c2);
}

// round 7
// speedup vs baseline: 1.9684x; 1.1498x over previous
#include <cuda_runtime.h>
#include <math.h>
#include <stdint.h>

#define NTOK 4096   // B*T
#define DM   1024
#define NH   16
#define DH   64
#define TT   2048
#define BB   2

#define KT      32          // gemm k-tile
#define NKT     (DM/KT)     // 32
#define LDS_S   36          // gemm padded k-stride (floats)
#define TILE_FL (128*LDS_S)
#define GEMM_SMEM (2*2*TILE_FL*4)

// retention smem strides (floats)
#define QS_STRIDE 68
#define KS_STRIDE 68
#define VS_STRIDE 72
#define RET_SMEM  ((2*64*QS_STRIDE + 2*64*KS_STRIDE + 2*64*VS_STRIDE) * 4)  // 106496 B

// Scratch (__device__ globals: allocation-free rule)
__device__ float g_Q[NTOK*DM];
__device__ float g_K[NTOK*DM];
__device__ float g_V[NTOK*DM];
__device__ float g_G[NTOK*DM];
__device__ float g_R[NTOK*DM];
__device__ float g_Y[NTOK*DM];
__device__ float g_Xr[NTOK*DM];
__device__ float g_Wt4[4*DM*DM];
__device__ float g_Wot[DM*DM];

__device__ __forceinline__ uint32_t smem_u32(const void* p) {
    uint32_t a;
    asm("{ .reg .u64 t; cvta.to.shared.u64 t, %1; cvt.u32.u64 %0, t; }" : "=r"(a) : "l"(p));
    return a;
}
__device__ __forceinline__ float tf32r(float x) {
    uint32_t u; asm("cvt.rna.tf32.f32 %0, %1;" : "=r"(u) : "f"(x));
    return __uint_as_float(u);
}
__device__ __forceinline__ void cpa16(uint32_t dst, const void* src) {
    asm volatile("cp.async.cg.shared.global [%0], [%1], 16;" :: "r"(dst), "l"(src) : "memory");
}
__device__ __forceinline__ void mma_tf32(float* c, const uint32_t* a, const uint32_t* b) {
    asm volatile(
        "mma.sync.aligned.m16n8k8.row.col.f32.tf32.tf32.f32 "
        "{%0,%1,%2,%3}, {%4,%5,%6,%7}, {%8,%9}, {%0,%1,%2,%3};"
        : "+f"(c[0]), "+f"(c[1]), "+f"(c[2]), "+f"(c[3])
        : "r"(a[0]), "r"(a[1]), "r"(a[2]), "r"(a[3]), "r"(b[0]), "r"(b[1]));
}

struct GemmCfg {
    float* out[4];
    const float* bias[4];
    int act[4];
};

// ---------------------------------------------------------------------------
// tf32 mma.sync GEMM (unchanged from round 6)
// ---------------------------------------------------------------------------
__global__ __launch_bounds__(256) void gemm_tc(
    const float* __restrict__ A, const float* __restrict__ Bt, GemmCfg cfg)
{
    extern __shared__ __align__(16) float smem[];
    float* As[2] = { smem,                smem + 2*TILE_FL };
    float* Bs[2] = { smem + TILE_FL,      smem + 3*TILE_FL };

    const int t = threadIdx.x;
    const int wid = t >> 5, lane = t & 31;
    const int wm = wid >> 2, wn = wid & 3;
    const int m0 = blockIdx.y * 128, n0 = blockIdx.x * 128;
    const int bsel = n0 >> 10;
    const int ncol0 = n0 & 1023;

    const int lq = lane >> 2;
    const int lr = lane & 3;

    const uint32_t sA0 = smem_u32(As[0]);
    const uint32_t sB0 = smem_u32(Bs[0]);
    const uint32_t bufStride = 2*TILE_FL*4;

    float acc[4][4][4];
    #pragma unroll
    for (int i = 0; i < 4; i++)
        #pragma unroll
        for (int j = 0; j < 4; j++)
            #pragma unroll
            for (int q = 0; q < 4; q++) acc[i][j][q] = 0.f;

    auto loadTile = [&](int kt, int buf) {
        const int k0 = kt * KT;
        #pragma unroll
        for (int i = 0; i < 4; i++) {
            int s = t + i * 256;
            int row = s >> 3, c4 = (s & 7) * 4;
            cpa16(sA0 + buf * bufStride + (row * LDS_S + c4) * 4,
                  A + (size_t)(m0 + row) * DM + k0 + c4);
            cpa16(sB0 + buf * bufStride + (row * LDS_S + c4) * 4,
                  Bt + (size_t)(n0 + row) * DM + k0 + c4);
        }
        asm volatile("cp.async.commit_group;" ::: "memory");
    };

    loadTile(0, 0);

    for (int kt = 0; kt < NKT; kt++) {
        if (kt + 1 < NKT) {
            loadTile(kt + 1, (kt + 1) & 1);
            asm volatile("cp.async.wait_group 1;" ::: "memory");
        } else {
            asm volatile("cp.async.wait_group 0;" ::: "memory");
        }
        __syncthreads();

        const float* a_s = As[kt & 1];
        const float* b_s = Bs[kt & 1];

        #pragma unroll
        for (int ks = 0; ks < KT / 8; ks++) {
            const int k0 = ks * 8;
            uint32_t af[4][4], bf[4][2];
            #pragma unroll
            for (int mi = 0; mi < 4; mi++) {
                const float* ap = a_s + (wm * 64 + mi * 16 + lq) * LDS_S + k0 + lr;
                af[mi][0] = __float_as_uint(ap[0]);
                af[mi][1] = __float_as_uint(ap[8 * LDS_S]);
                af[mi][2] = __float_as_uint(ap[4]);
                af[mi][3] = __float_as_uint(ap[8 * LDS_S + 4]);
            }
            #pragma unroll
            for (int ni = 0; ni < 4; ni++) {
                const float* bp = b_s + (wn * 32 + ni * 8 + lq) * LDS_S + k0 + lr;
                bf[ni][0] = __float_as_uint(bp[0]);
                bf[ni][1] = __float_as_uint(bp[4]);
            }
            #pragma unroll
            for (int mi = 0; mi < 4; mi++)
                #pragma unroll
                for (int ni = 0; ni < 4; ni++)
                    mma_tf32(acc[mi][ni], af[mi], bf[ni]);
        }
        __syncthreads();
    }

    float* outp = cfg.out[bsel];
    const float* bp = cfg.bias[bsel];
    const int act = cfg.act[bsel];

    #pragma unroll
    for (int mi = 0; mi < 4; mi++) {
        #pragma unroll
        for (int ni = 0; ni < 4; ni++) {
            const int col = ncol0 + wn * 32 + ni * 8 + lr * 2;
            float b0 = 0.f, b1 = 0.f;
            if (bp) { b0 = bp[col]; b1 = bp[col + 1]; }
            #pragma unroll
            for (int h = 0; h < 2; h++) {
                const int row = m0 + wm * 64 + mi * 16 + lq + h * 8;
                float z0 = acc[mi][ni][h * 2 + 0] + b0;
                float z1 = acc[mi][ni][h * 2 + 1] + b1;
                if (act) {
                    z0 = z0 / (1.0f + expf(-z0));
                    z1 = z1 / (1.0f + expf(-z1));
                }
                float2 v = make_float2(z0, z1);
                *(float2*)(outp + (size_t)row * DM + col) = v;
            }
        }
    }
}

// ---------------------------------------------------------------------------
// Prep kernels
// ---------------------------------------------------------------------------
__global__ __launch_bounds__(256) void round_copy(const float* __restrict__ in,
                                                  float* __restrict__ out)
{
    size_t i = ((size_t)blockIdx.x * 256 + threadIdx.x) * 4;
    float4 v = *(const float4*)(in + i);
    v.x = tf32r(v.x); v.y = tf32r(v.y); v.z = tf32r(v.z); v.w = tf32r(v.w);
    *(float4*)(out + i) = v;
}

__global__ __launch_bounds__(256) void transpose_round(const float* __restrict__ W,
                                                       float* __restrict__ Wt)
{
    __shared__ float tile[32][33];
    const int k0 = blockIdx.x * 32, n0 = blockIdx.y * 32;
    const int tx = threadIdx.x & 31, ty = threadIdx.x >> 5;
    #pragma unroll
    for (int i = 0; i < 32; i += 8)
        tile[ty + i][tx] = W[(size_t)(k0 + ty + i) * DM + n0 + tx];
    __syncthreads();
    #pragma unroll
    for (int i = 0; i < 32; i += 8)
        Wt[(size_t)(n0 + ty + i) * DM + k0 + tx] = tf32r(tile[tx][ty + i]);
}

// ---------------------------------------------------------------------------
// Retention on tensor cores: per CTA = 64 q-rows x (head, batch).
// For each 64-token kv block: S = Q K^T (MMA), decay+causal in regs,
// rna-round S -> SMEM, O += S V (MMA). K/V double-buffered cp.async.
// 8 warps as 4(m) x 2(n); warp tile 16x32.
// ---------------------------------------------------------------------------
__global__ __launch_bounds__(256) void retention_tc(
    const float* __restrict__ Q, const float* __restrict__ K,
    const float* __restrict__ V, float* __restrict__ R)
{
    extern __shared__ __align__(16) float sm[];
    float* Qs = sm;                                   // 64 x 68
    float* Ss = Qs + 64*QS_STRIDE;                    // 64 x 68
    float* Ks = Ss + 64*QS_STRIDE;                    // 2 x 64 x 68
    float* Vs = Ks + 2*64*KS_STRIDE;                  // 2 x 64 x 72

    const int qb = blockIdx.x, h = blockIdx.y, b = blockIdx.z;
    const int t = threadIdx.x;
    const int wid = t >> 5, lane = t & 31;
    const int wm = wid >> 1, wn = wid & 1;            // 4 x 2 warp grid
    const int lq = lane >> 2, lr = lane & 3;
    const size_t base = (size_t)b * TT * DM + (size_t)h * DH;
    const int t0 = qb * 64;

    const uint32_t sQ = smem_u32(Qs), sK = smem_u32(Ks), sV = smem_u32(Vs);

    // Q tile
    #pragma unroll
    for (int i = 0; i < 4; i++) {
        int s = t + i * 256;
        int row = s >> 4, c4 = (s & 15) * 4;
        cpa16(sQ + (row * QS_STRIDE + c4) * 4, Q + base + (size_t)(t0 + row) * DM + c4);
    }
    asm volatile("cp.async.commit_group;" ::: "memory");

    // decay window
    const float gamma = 1.0f - exp2f(-(float)(5 + h));
    const float l2g   = log2f(gamma);                 // negative
    float diffmax = 24.0f / (-l2g);
    int nb_back = (diffmax > 1.0e8f) ? qb : ((int)(diffmax * (1.0f / 64.0f)) + 2);
    int sb0 = qb - nb_back; if (sb0 < 0) sb0 = 0;
    const int nit = qb - sb0 + 1;

    // per-thread decay factors (fixed local row/col positions)
    float rowf[2], colf[8];
    #pragma unroll
    for (int i = 0; i < 2; i++)
        rowf[i] = exp2f(l2g * (float)(wm * 16 + lq + 8 * i)) * 0.125f;
    #pragma unroll
    for (int ni = 0; ni < 4; ni++)
        #pragma unroll
        for (int j = 0; j < 2; j++)
            colf[ni * 2 + j] = exp2f(-l2g * (float)(wn * 32 + ni * 8 + 2 * lr + j));

    auto loadKV = [&](int sb, int buf) {
        #pragma unroll
        for (int i = 0; i < 4; i++) {
            int s = t + i * 256;
            int row = s >> 4, c4 = (s & 15) * 4;
            cpa16(sK + (buf * 64 * KS_STRIDE + row * KS_STRIDE + c4) * 4,
                  K + base + (size_t)(sb * 64 + row) * DM + c4);
            cpa16(sV + (buf * 64 * VS_STRIDE + row * VS_STRIDE + c4) * 4,
                  V + base + (size_t)(sb * 64 + row) * DM + c4);
        }
        asm volatile("cp.async.commit_group;" ::: "memory");
    };

    loadKV(sb0, 0);

    float oacc[4][4];
    #pragma unroll
    for (int ni = 0; ni < 4; ni++)
        #pragma unroll
        for (int q = 0; q < 4; q++) oacc[ni][q] = 0.f;

    for (int it = 0; it < nit; it++) {
        const int sb = sb0 + it;
        const int buf = it & 1;
        asm volatile("cp.async.wait_group 0;" ::: "memory");
        __syncthreads();

        // ---- S = Q K^T ----
        float sacc[4][4];
        #pragma unroll
        for (int ni = 0; ni < 4; ni++)
            #pragma unroll
            for (int q = 0; q < 4; q++) sacc[ni][q] = 0.f;

        const float* kbuf = Ks + buf * 64 * KS_STRIDE;
        #pragma unroll
        for (int kc = 0; kc < 8; kc++) {
            const int k0 = kc * 8;
            uint32_t af[4];
            const float* ap = Qs + (wm * 16 + lq) * QS_STRIDE + k0 + lr;
            af[0] = __float_as_uint(ap[0]);
            af[1] = __float_as_uint(ap[8 * QS_STRIDE]);
            af[2] = __float_as_uint(ap[4]);
            af[3] = __float_as_uint(ap[8 * QS_STRIDE + 4]);
            #pragma unroll
            for (int ni = 0; ni < 4; ni++) {
                const float* bp = kbuf + (wn * 32 + ni * 8 + lq) * KS_STRIDE + k0 + lr;
                uint32_t bf[2] = { __float_as_uint(bp[0]), __float_as_uint(bp[4]) };
                mma_tf32(sacc[ni], af, bf);
            }
        }

        // prefetch next KV block (overlaps decay + O phase)
        if (it + 1 < nit) loadKV(sb + 1, (it + 1) & 1);
        else asm volatile("cp.async.commit_group;" ::: "memory");

        // ---- decay + causal, rna-round, store S ----
        const float pb = exp2f(l2g * (float)(64 * (qb - sb)));
        const bool diag = (sb == qb);
        #pragma unroll
        for (int ni = 0; ni < 4; ni++) {
            const int nl0 = wn * 32 + ni * 8 + 2 * lr;
            #pragma unroll
            for (int half = 0; half < 2; half++) {
                const int mloc = wm * 16 + lq + half * 8;
                const float wr = rowf[half] * pb;
                float v0 = sacc[ni][half * 2 + 0] * (wr * colf[ni * 2 + 0]);
                float v1 = sacc[ni][half * 2 + 1] * (wr * colf[ni * 2 + 1]);
                if (diag && nl0     > mloc) v0 = 0.f;
                if (diag && nl0 + 1 > mloc) v1 = 0.f;
                float2 st = make_float2(tf32r(v0), tf32r(v1));
                *(float2*)&Ss[mloc * QS_STRIDE + nl0] = st;
            }
        }
        __syncthreads();

        // ---- O += S V ----
        const float* vbuf = Vs + buf * 64 * VS_STRIDE;
        #pragma unroll
        for (int kc = 0; kc < 8; kc++) {
            const int k0 = kc * 8;
            uint32_t af[4];
            const float* ap = Ss + (wm * 16 + lq) * QS_STRIDE + k0 + lr;
            af[0] = __float_as_uint(ap[0]);
            af[1] = __float_as_uint(ap[8 * QS_STRIDE]);
            af[2] = __float_as_uint(ap[4]);
            af[3] = __float_as_uint(ap[8 * QS_STRIDE + 4]);
            #pragma unroll
            for (int ni = 0; ni < 4; ni++) {
                // B[n][k] = V[k][n]: b0 at row k0+lr, b1 at row k0+lr+4
                const float* bp = vbuf + (k0 + lr) * VS_STRIDE + wn * 32 + ni * 8 + lq;
                uint32_t bf[2] = { __float_as_uint(bp[0]),
                                   __float_as_uint(bp[4 * VS_STRIDE]) };
                mma_tf32(oacc[ni], af, bf);
            }
        }
        __syncthreads();
    }

    // write O (head-concat layout)
    #pragma unroll
    for (int ni = 0; ni < 4; ni++) {
        const int col = wn * 32 + ni * 8 + 2 * lr;
        #pragma unroll
        for (int half = 0; half < 2; half++) {
            const int row = t0 + wm * 16 + lq + half * 8;
            float2 v = make_float2(oacc[ni][half * 2 + 0], oacc[ni][half * 2 + 1]);
            *(float2*)(R + base + (size_t)row * DM + col) = v;
        }
    }
}

// ---------------------------------------------------------------------------
// LayerNorm * gate (tf32-rounds Y for the output GEMM)
// ---------------------------------------------------------------------------
__global__ __launch_bounds__(256) void ln_gate_kernel(
    const float* __restrict__ R, const float* __restrict__ G,
    const float* __restrict__ lng, const float* __restrict__ lnb,
    float* __restrict__ Y)
{
    __shared__ float red[8];
    const int row = blockIdx.x;
    const int t = threadIdx.x;
    const size_t off = (size_t)row * DM + t * 4;

    float4 x = *(const float4*)(R + off);

    float s = x.x + x.y + x.z + x.w;
    #pragma unroll
    for (int o = 16; o > 0; o >>= 1) s += __shfl_xor_sync(0xffffffffu, s, o);
    if ((t & 31) == 0) red[t >> 5] = s;
    __syncthreads();
    float tot = red[0] + red[1] + red[2] + red[3] + red[4] + red[5] + red[6] + red[7];
    const float mu = tot * (1.0f / 1024.0f);

    float d0 = x.x - mu, d1 = x.y - mu, d2 = x.z - mu, d3 = x.w - mu;
    float sq = d0 * d0 + d1 * d1 + d2 * d2 + d3 * d3;
    #pragma unroll
    for (int o = 16; o > 0; o >>= 1) sq += __shfl_xor_sync(0xffffffffu, sq, o);
    __syncthreads();
    if ((t & 31) == 0) red[t >> 5] = sq;
    __syncthreads();
    float totsq = red[0] + red[1] + red[2] + red[3] + red[4] + red[5] + red[6] + red[7];
    const float rstd = rsqrtf(totsq * (1.0f / 1024.0f) + 1e-3f);

    float4 g4 = *(const float4*)(lng + t * 4);
    float4 b4 = *(const float4*)(lnb + t * 4);
    float4 gt = *(const float4*)(G + off);

    float4 y;
    y.x = tf32r((d0 * rstd * g4.x + b4.x) * gt.x);
    y.y = tf32r((d1 * rstd * g4.y + b4.y) * gt.y);
    y.z = tf32r((d2 * rstd * g4.z + b4.z) * gt.z);
    y.w = tf32r((d3 * rstd * g4.w + b4.w) * gt.w);
    *(float4*)(Y + off) = y;
}

// ---------------------------------------------------------------------------
extern "C" void kernel_launch(void* const* d_in, const int* in_sizes, int n_in,
                              void* d_out, int out_size)
{
    const float* x   = (const float*)d_in[0];
    const float* Wq  = (const float*)d_in[1];
    const float* Wk  = (const float*)d_in[2];
    const float* Wv  = (const float*)d_in[3];
    const float* Wg  = (const float*)d_in[4];
    const float* bg  = (const float*)d_in[5];
    const float* Wo  = (const float*)d_in[6];
    const float* bo  = (const float*)d_in[7];
    const float* lng = (const float*)d_in[8];
    const float* lnb = (const float*)d_in[9];

    float *Q, *K, *V, *G, *R, *Y, *Xr, *Wt4, *Wot;
    cudaGetSymbolAddress((void**)&Q,  g_Q);
    cudaGetSymbolAddress((void**)&K,  g_K);
    cudaGetSymbolAddress((void**)&V,  g_V);
    cudaGetSymbolAddress((void**)&G,  g_G);
    cudaGetSymbolAddress((void**)&R,  g_R);
    cudaGetSymbolAddress((void**)&Y,  g_Y);
    cudaGetSymbolAddress((void**)&Xr, g_Xr);
    cudaGetSymbolAddress((void**)&Wt4, g_Wt4);
    cudaGetSymbolAddress((void**)&Wot, g_Wot);

    round_copy<<<(NTOK * DM) / (256 * 4), 256>>>(x, Xr);
    dim3 tb(256), tg(32, 32);
    transpose_round<<<tg, tb>>>(Wq, Wt4 + 0 * DM * DM);
    transpose_round<<<tg, tb>>>(Wk, Wt4 + 1 * DM * DM);
    transpose_round<<<tg, tb>>>(Wv, Wt4 + 2 * DM * DM);
    transpose_round<<<tg, tb>>>(Wg, Wt4 + 3 * DM * DM);
    transpose_round<<<tg, tb>>>(Wo, Wot);

    cudaFuncSetAttribute(gemm_tc, cudaFuncAttributeMaxDynamicSharedMemorySize, GEMM_SMEM);

    GemmCfg c1;
    c1.out[0] = Q;  c1.out[1] = K;  c1.out[2] = V;  c1.out[3] = G;
    c1.bias[0] = nullptr; c1.bias[1] = nullptr; c1.bias[2] = nullptr; c1.bias[3] = bg;
    c1.act[0] = 0; c1.act[1] = 0; c1.act[2] = 0; c1.act[3] = 1;
    gemm_tc<<<dim3(32, 32), 256, GEMM_SMEM>>>(Xr, Wt4, c1);

    cudaFuncSetAttribute(retention_tc, cudaFuncAttributeMaxDynamicSharedMemorySize, RET_SMEM);
    retention_tc<<<dim3(TT / 64, NH, BB), 256, RET_SMEM>>>(Q, K, V, R);

    ln_gate_kernel<<<NTOK, 256>>>(R, G, lng, lnb, Y);

    GemmCfg c2;
    c2.out[0] = (float*)d_out; c2.out[1] = nullptr; c2.out[2] = nullptr; c2.out[3] = nullptr;
    c2.bias[0] = bo; c2.bias[1] = nullptr; c2.bias[2] = nullptr; c2.bias[3] = nullptr;
    c2.act[0] = 0; c2.act[1] = 0; c2.act[2] = 0; c2.act[3] = 0;
    gemm_tc<<<dim3(8, 32), 256, GEMM_SMEM>>>(Y, Wot, c2);
}

// round 9
// speedup vs baseline: 3.2671x; 1.6597x over previous
#include <cuda_runtime.h>
#include <math.h>
#include <stdint.h>

#define NTOK 4096   // B*T
#define DM   1024
#define NH   16
#define DH   64
#define TT   2048
#define BB   2

#define KT      32          // gemm k-tile
#define NKT     (DM/KT)     // 32
#define LDS_S   36          // gemm padded k-stride (floats)
#define TILE_FL (128*LDS_S)
#define GEMM_SMEM (2*2*TILE_FL*4)

// retention smem strides (floats)
#define QS_STRIDE 68
#define KS_STRIDE 68
#define VS_STRIDE 72
#define RET_SMEM  ((2*64*QS_STRIDE + 2*64*KS_STRIDE + 2*64*VS_STRIDE) * 4)  // 106496 B

// Scratch (__device__ globals: allocation-free rule)
__device__ float g_Q[NTOK*DM];
__device__ float g_K[NTOK*DM];
__device__ float g_V[NTOK*DM];
__device__ float g_G[NTOK*DM];
__device__ float g_R[NTOK*DM];
__device__ float g_Y[NTOK*DM];
__device__ float g_Xr[NTOK*DM];
__device__ float g_Wt4[4*DM*DM];
__device__ float g_Wot[DM*DM];

__device__ __forceinline__ uint32_t smem_u32(const void* p) {
    uint32_t a;
    asm("{ .reg .u64 t; cvta.to.shared.u64 t, %1; cvt.u32.u64 %0, t; }" : "=r"(a) : "l"(p));
    return a;
}
__device__ __forceinline__ float tf32r(float x) {
    uint32_t u; asm("cvt.rna.tf32.f32 %0, %1;" : "=r"(u) : "f"(x));
    return __uint_as_float(u);
}
__device__ __forceinline__ void cpa16(uint32_t dst, const void* src) {
    asm volatile("cp.async.cg.shared.global [%0], [%1], 16;" :: "r"(dst), "l"(src) : "memory");
}
__device__ __forceinline__ void mma_tf32(float* c, const uint32_t* a, const uint32_t* b) {
    asm volatile(
        "mma.sync.aligned.m16n8k8.row.col.f32.tf32.tf32.f32 "
        "{%0,%1,%2,%3}, {%4,%5,%6,%7}, {%8,%9}, {%0,%1,%2,%3};"
        : "+f"(c[0]), "+f"(c[1]), "+f"(c[2]), "+f"(c[3])
        : "r"(a[0]), "r"(a[1]), "r"(a[2]), "r"(a[3]), "r"(b[0]), "r"(b[1]));
}

struct GemmCfg {
    float* out[4];
    const float* bias[4];
    int act[4];
};

// ---------------------------------------------------------------------------
// tf32 mma.sync GEMM (unchanged — ~86% of legacy tensor peak)
// ---------------------------------------------------------------------------
__global__ __launch_bounds__(256) void gemm_tc(
    const float* __restrict__ A, const float* __restrict__ Bt, GemmCfg cfg)
{
    extern __shared__ __align__(16) float smem[];
    float* As[2] = { smem,                smem + 2*TILE_FL };
    float* Bs[2] = { smem + TILE_FL,      smem + 3*TILE_FL };

    const int t = threadIdx.x;
    const int wid = t >> 5, lane = t & 31;
    const int wm = wid >> 2, wn = wid & 3;
    const int m0 = blockIdx.y * 128, n0 = blockIdx.x * 128;
    const int bsel = n0 >> 10;
    const int ncol0 = n0 & 1023;

    const int lq = lane >> 2;
    const int lr = lane & 3;

    const uint32_t sA0 = smem_u32(As[0]);
    const uint32_t sB0 = smem_u32(Bs[0]);
    const uint32_t bufStride = 2*TILE_FL*4;

    float acc[4][4][4];
    #pragma unroll
    for (int i = 0; i < 4; i++)
        #pragma unroll
        for (int j = 0; j < 4; j++)
            #pragma unroll
            for (int q = 0; q < 4; q++) acc[i][j][q] = 0.f;

    auto loadTile = [&](int kt, int buf) {
        const int k0 = kt * KT;
        #pragma unroll
        for (int i = 0; i < 4; i++) {
            int s = t + i * 256;
            int row = s >> 3, c4 = (s & 7) * 4;
            cpa16(sA0 + buf * bufStride + (row * LDS_S + c4) * 4,
                  A + (size_t)(m0 + row) * DM + k0 + c4);
            cpa16(sB0 + buf * bufStride + (row * LDS_S + c4) * 4,
                  Bt + (size_t)(n0 + row) * DM + k0 + c4);
        }
        asm volatile("cp.async.commit_group;" ::: "memory");
    };

    loadTile(0, 0);

    for (int kt = 0; kt < NKT; kt++) {
        if (kt + 1 < NKT) {
            loadTile(kt + 1, (kt + 1) & 1);
            asm volatile("cp.async.wait_group 1;" ::: "memory");
        } else {
            asm volatile("cp.async.wait_group 0;" ::: "memory");
        }
        __syncthreads();

        const float* a_s = As[kt & 1];
        const float* b_s = Bs[kt & 1];

        #pragma unroll
        for (int ks = 0; ks < KT / 8; ks++) {
            const int k0 = ks * 8;
            uint32_t af[4][4], bf[4][2];
            #pragma unroll
            for (int mi = 0; mi < 4; mi++) {
                const float* ap = a_s + (wm * 64 + mi * 16 + lq) * LDS_S + k0 + lr;
                af[mi][0] = __float_as_uint(ap[0]);
                af[mi][1] = __float_as_uint(ap[8 * LDS_S]);
                af[mi][2] = __float_as_uint(ap[4]);
                af[mi][3] = __float_as_uint(ap[8 * LDS_S + 4]);
            }
            #pragma unroll
            for (int ni = 0; ni < 4; ni++) {
                const float* bp = b_s + (wn * 32 + ni * 8 + lq) * LDS_S + k0 + lr;
                bf[ni][0] = __float_as_uint(bp[0]);
                bf[ni][1] = __float_as_uint(bp[4]);
            }
            #pragma unroll
            for (int mi = 0; mi < 4; mi++)
                #pragma unroll
                for (int ni = 0; ni < 4; ni++)
                    mma_tf32(acc[mi][ni], af[mi], bf[ni]);
        }
        __syncthreads();
    }

    float* outp = cfg.out[bsel];
    const float* bp = cfg.bias[bsel];
    const int act = cfg.act[bsel];

    #pragma unroll
    for (int mi = 0; mi < 4; mi++) {
        #pragma unroll
        for (int ni = 0; ni < 4; ni++) {
            const int col = ncol0 + wn * 32 + ni * 8 + lr * 2;
            float b0 = 0.f, b1 = 0.f;
            if (bp) { b0 = bp[col]; b1 = bp[col + 1]; }
            #pragma unroll
            for (int h = 0; h < 2; h++) {
                const int row = m0 + wm * 64 + mi * 16 + lq + h * 8;
                float z0 = acc[mi][ni][h * 2 + 0] + b0;
                float z1 = acc[mi][ni][h * 2 + 1] + b1;
                if (act) {
                    z0 = z0 / (1.0f + expf(-z0));
                    z1 = z1 / (1.0f + expf(-z1));
                }
                float2 v = make_float2(z0, z1);
                *(float2*)(outp + (size_t)row * DM + col) = v;
            }
        }
    }
}

// ---------------------------------------------------------------------------
// Prep kernels. transpose_round2 handles two weights (blockIdx.z selects) so
// prep = exactly 4 launches and retention lands at ncu capture index 5.
// ---------------------------------------------------------------------------
__global__ __launch_bounds__(256) void round_copy(const float* __restrict__ in,
                                                  float* __restrict__ out)
{
    size_t i = ((size_t)blockIdx.x * 256 + threadIdx.x) * 4;
    float4 v = *(const float4*)(in + i);
    v.x = tf32r(v.x); v.y = tf32r(v.y); v.z = tf32r(v.z); v.w = tf32r(v.w);
    *(float4*)(out + i) = v;
}

__global__ __launch_bounds__(256) void transpose_round2(
    const float* __restrict__ Wa, float* __restrict__ Wta,
    const float* __restrict__ Wb, float* __restrict__ Wtb)
{
    __shared__ float tile[32][33];
    const float* W  = blockIdx.z ? Wb  : Wa;
    float*       Wt = blockIdx.z ? Wtb : Wta;
    const int k0 = blockIdx.x * 32, n0 = blockIdx.y * 32;
    const int tx = threadIdx.x & 31, ty = threadIdx.x >> 5;
    #pragma unroll
    for (int i = 0; i < 32; i += 8)
        tile[ty + i][tx] = W[(size_t)(k0 + ty + i) * DM + n0 + tx];
    __syncthreads();
    #pragma unroll
    for (int i = 0; i < 32; i += 8)
        Wt[(size_t)(n0 + ty + i) * DM + k0 + tx] = tf32r(tile[tx][ty + i]);
}

// ---------------------------------------------------------------------------
// Retention on tensor cores. Flat grid with WORK-DESCENDING decode:
// heaviest CTAs (high qb) launch first, light ones backfill the tail.
// ---------------------------------------------------------------------------
__global__ __launch_bounds__(256) void retention_tc(
    const float* __restrict__ Q, const float* __restrict__ K,
    const float* __restrict__ V, float* __restrict__ R)
{
    extern __shared__ __align__(16) float sm[];
    float* Qs = sm;                                   // 64 x 68
    float* Ss = Qs + 64*QS_STRIDE;                    // 64 x 68
    float* Ks = Ss + 64*QS_STRIDE;                    // 2 x 64 x 68
    float* Vs = Ks + 2*64*KS_STRIDE;                  // 2 x 64 x 72

    // work-descending decode: qb major (desc), head minor (desc), batch last
    const int idx = blockIdx.x;
    const int qb = (TT/64 - 1) - (idx >> 5);          // 31..0
    const int rem = idx & 31;
    const int h = 15 - (rem >> 1);
    const int b = rem & 1;

    const int t = threadIdx.x;
    const int wid = t >> 5, lane = t & 31;
    const int wm = wid >> 1, wn = wid & 1;            // 4 x 2 warp grid
    const int lq = lane >> 2, lr = lane & 3;
    const size_t base = (size_t)b * TT * DM + (size_t)h * DH;
    const int t0 = qb * 64;

    const uint32_t sQ = smem_u32(Qs), sK = smem_u32(Ks), sV = smem_u32(Vs);

    // Q tile
    #pragma unroll
    for (int i = 0; i < 4; i++) {
        int s = t + i * 256;
        int row = s >> 4, c4 = (s & 15) * 4;
        cpa16(sQ + (row * QS_STRIDE + c4) * 4, Q + base + (size_t)(t0 + row) * DM + c4);
    }
    asm volatile("cp.async.commit_group;" ::: "memory");

    // decay window
    const float gamma = 1.0f - exp2f(-(float)(5 + h));
    const float l2g   = log2f(gamma);                 // negative
    float diffmax = 24.0f / (-l2g);
    int nb_back = (diffmax > 1.0e8f) ? qb : ((int)(diffmax * (1.0f / 64.0f)) + 2);
    int sb0 = qb - nb_back; if (sb0 < 0) sb0 = 0;
    const int nit = qb - sb0 + 1;

    float rowf[2], colf[8];
    #pragma unroll
    for (int i = 0; i < 2; i++)
        rowf[i] = exp2f(l2g * (float)(wm * 16 + lq + 8 * i)) * 0.125f;
    #pragma unroll
    for (int ni = 0; ni < 4; ni++)
        #pragma unroll
        for (int j = 0; j < 2; j++)
            colf[ni * 2 + j] = exp2f(-l2g * (float)(wn * 32 + ni * 8 + 2 * lr + j));

    auto loadKV = [&](int sb, int buf) {
        #pragma unroll
        for (int i = 0; i < 4; i++) {
            int s = t + i * 256;
            int row = s >> 4, c4 = (s & 15) * 4;
            cpa16(sK + (buf * 64 * KS_STRIDE + row * KS_STRIDE + c4) * 4,
                  K + base + (size_t)(sb * 64 + row) * DM + c4);
            cpa16(sV + (buf * 64 * VS_STRIDE + row * VS_STRIDE + c4) * 4,
                  V + base + (size_t)(sb * 64 + row) * DM + c4);
        }
        asm volatile("cp.async.commit_group;" ::: "memory");
    };

    loadKV(sb0, 0);

    float oacc[4][4];
    #pragma unroll
    for (int ni = 0; ni < 4; ni++)
        #pragma unroll
        for (int q = 0; q < 4; q++) oacc[ni][q] = 0.f;

    for (int it = 0; it < nit; it++) {
        const int sb = sb0 + it;
        const int buf = it & 1;
        asm volatile("cp.async.wait_group 0;" ::: "memory");
        __syncthreads();

        // ---- S = Q K^T ----
        float sacc[4][4];
        #pragma unroll
        for (int ni = 0; ni < 4; ni++)
            #pragma unroll
            for (int q = 0; q < 4; q++) sacc[ni][q] = 0.f;

        const float* kbuf = Ks + buf * 64 * KS_STRIDE;
        #pragma unroll
        for (int kc = 0; kc < 8; kc++) {
            const int k0 = kc * 8;
            uint32_t af[4];
            const float* ap = Qs + (wm * 16 + lq) * QS_STRIDE + k0 + lr;
            af[0] = __float_as_uint(ap[0]);
            af[1] = __float_as_uint(ap[8 * QS_STRIDE]);
            af[2] = __float_as_uint(ap[4]);
            af[3] = __float_as_uint(ap[8 * QS_STRIDE + 4]);
            #pragma unroll
            for (int ni = 0; ni < 4; ni++) {
                const float* bp = kbuf + (wn * 32 + ni * 8 + lq) * KS_STRIDE + k0 + lr;
                uint32_t bf[2] = { __float_as_uint(bp[0]), __float_as_uint(bp[4]) };
                mma_tf32(sacc[ni], af, bf);
            }
        }

        if (it + 1 < nit) loadKV(sb + 1, (it + 1) & 1);
        else asm volatile("cp.async.commit_group;" ::: "memory");

        // ---- decay + causal, rna-round, store S ----
        const float pb = exp2f(l2g * (float)(64 * (qb - sb)));
        const bool diag = (sb == qb);
        #pragma unroll
        for (int ni = 0; ni < 4; ni++) {
            const int nl0 = wn * 32 + ni * 8 + 2 * lr;
            #pragma unroll
            for (int half = 0; half < 2; half++) {
                const int mloc = wm * 16 + lq + half * 8;
                const float wr = rowf[half] * pb;
                float v0 = sacc[ni][half * 2 + 0] * (wr * colf[ni * 2 + 0]);
                float v1 = sacc[ni][half * 2 + 1] * (wr * colf[ni * 2 + 1]);
                if (diag && nl0     > mloc) v0 = 0.f;
                if (diag && nl0 + 1 > mloc) v1 = 0.f;
                float2 st = make_float2(tf32r(v0), tf32r(v1));
                *(float2*)&Ss[mloc * QS_STRIDE + nl0] = st;
            }
        }
        __syncthreads();

        // ---- O += S V ----
        const float* vbuf = Vs + buf * 64 * VS_STRIDE;
        #pragma unroll
        for (int kc = 0; kc < 8; kc++) {
            const int k0 = kc * 8;
            uint32_t af[4];
            const float* ap = Ss + (wm * 16 + lq) * QS_STRIDE + k0 + lr;
            af[0] = __float_as_uint(ap[0]);
            af[1] = __float_as_uint(ap[8 * QS_STRIDE]);
            af[2] = __float_as_uint(ap[4]);
            af[3] = __float_as_uint(ap[8 * QS_STRIDE + 4]);
            #pragma unroll
            for (int ni = 0; ni < 4; ni++) {
                const float* bp = vbuf + (k0 + lr) * VS_STRIDE + wn * 32 + ni * 8 + lq;
                uint32_t bf[2] = { __float_as_uint(bp[0]),
                                   __float_as_uint(bp[4 * VS_STRIDE]) };
                mma_tf32(oacc[ni], af, bf);
            }
        }
        __syncthreads();
    }

    #pragma unroll
    for (int ni = 0; ni < 4; ni++) {
        const int col = wn * 32 + ni * 8 + 2 * lr;
        #pragma unroll
        for (int half = 0; half < 2; half++) {
            const int row = t0 + wm * 16 + lq + half * 8;
            float2 v = make_float2(oacc[ni][half * 2 + 0], oacc[ni][half * 2 + 1]);
            *(float2*)(R + base + (size_t)row * DM + col) = v;
        }
    }
}

// ---------------------------------------------------------------------------
// LayerNorm * gate
// ---------------------------------------------------------------------------
__global__ __launch_bounds__(256) void ln_gate_kernel(
    const float* __restrict__ R, const float* __restrict__ G,
    const float* __restrict__ lng, const float* __restrict__ lnb,
    float* __restrict__ Y)
{
    __shared__ float red[8];
    const int row = blockIdx.x;
    const int t = threadIdx.x;
    const size_t off = (size_t)row * DM + t * 4;

    float4 x = *(const float4*)(R + off);

    float s = x.x + x.y + x.z + x.w;
    #pragma unroll
    for (int o = 16; o > 0; o >>= 1) s += __shfl_xor_sync(0xffffffffu, s, o);
    if ((t & 31) == 0) red[t >> 5] = s;
    __syncthreads();
    float tot = red[0] + red[1] + red[2] + red[3] + red[4] + red[5] + red[6] + red[7];
    const float mu = tot * (1.0f / 1024.0f);

    float d0 = x.x - mu, d1 = x.y - mu, d2 = x.z - mu, d3 = x.w - mu;
    float sq = d0 * d0 + d1 * d1 + d2 * d2 + d3 * d3;
    #pragma unroll
    for (int o = 16; o > 0; o >>= 1) sq += __shfl_xor_sync(0xffffffffu, sq, o);
    __syncthreads();
    if ((t & 31) == 0) red[t >> 5] = sq;
    __syncthreads();
    float totsq = red[0] + red[1] + red[2] + red[3] + red[4] + red[5] + red[6] + red[7];
    const float rstd = rsqrtf(totsq * (1.0f / 1024.0f) + 1e-3f);

    float4 g4 = *(const float4*)(lng + t * 4);
    float4 b4 = *(const float4*)(lnb + t * 4);
    float4 gt = *(const float4*)(G + off);

    float4 y;
    y.x = tf32r((d0 * rstd * g4.x + b4.x) * gt.x);
    y.y = tf32r((d1 * rstd * g4.y + b4.y) * gt.y);
    y.z = tf32r((d2 * rstd * g4.z + b4.z) * gt.z);
    y.w = tf32r((d3 * rstd * g4.w + b4.w) * gt.w);
    *(float4*)(Y + off) = y;
}

// ---------------------------------------------------------------------------
extern "C" void kernel_launch(void* const* d_in, const int* in_sizes, int n_in,
                              void* d_out, int out_size)
{
    const float* x   = (const float*)d_in[0];
    const float* Wq  = (const float*)d_in[1];
    const float* Wk  = (const float*)d_in[2];
    const float* Wv  = (const float*)d_in[3];
    const float* Wg  = (const float*)d_in[4];
    const float* bg  = (const float*)d_in[5];
    const float* Wo  = (const float*)d_in[6];
    const float* bo  = (const float*)d_in[7];
    const float* lng = (const float*)d_in[8];
    const float* lnb = (const float*)d_in[9];

    float *Q, *K, *V, *G, *R, *Y, *Xr, *Wt4, *Wot;
    cudaGetSymbolAddress((void**)&Q,  g_Q);
    cudaGetSymbolAddress((void**)&K,  g_K);
    cudaGetSymbolAddress((void**)&V,  g_V);
    cudaGetSymbolAddress((void**)&G,  g_G);
    cudaGetSymbolAddress((void**)&R,  g_R);
    cudaGetSymbolAddress((void**)&Y,  g_Y);
    cudaGetSymbolAddress((void**)&Xr, g_Xr);
    cudaGetSymbolAddress((void**)&Wt4, g_Wt4);
    cudaGetSymbolAddress((void**)&Wot, g_Wot);

    // Launch order fixed so ncu (-s 5 -c 1) profiles retention_tc (index 5):
    // 0: round_copy, 1-2: transpose_round2, 3: transpose_round2(Wo dup),
    // 4: gemm QKVG, 5: retention, 6: ln, 7: gemm out
    round_copy<<<(NTOK * DM) / (256 * 4), 256>>>(x, Xr);
    dim3 tg2(32, 32, 2);
    transpose_round2<<<tg2, 256>>>(Wq, Wt4 + 0 * DM * DM, Wk, Wt4 + 1 * DM * DM);
    transpose_round2<<<tg2, 256>>>(Wv, Wt4 + 2 * DM * DM, Wg, Wt4 + 3 * DM * DM);
    transpose_round2<<<dim3(32, 32, 1), 256>>>(Wo, Wot, Wo, Wot);

    cudaFuncSetAttribute(gemm_tc, cudaFuncAttributeMaxDynamicSharedMemorySize, GEMM_SMEM);

    GemmCfg c1;
    c1.out[0] = Q;  c1.out[1] = K;  c1.out[2] = V;  c1.out[3] = G;
    c1.bias[0] = nullptr; c1.bias[1] = nullptr; c1.bias[2] = nullptr; c1.bias[3] = bg;
    c1.act[0] = 0; c1.act[1] = 0; c1.act[2] = 0; c1.act[3] = 1;
    gemm_tc<<<dim3(32, 32), 256, GEMM_SMEM>>>(Xr, Wt4, c1);

    cudaFuncSetAttribute(retention_tc, cudaFuncAttributeMaxDynamicSharedMemorySize, RET_SMEM);
    retention_tc<<<dim3((TT/64) * NH * BB), 256, RET_SMEM>>>(Q, K, V, R);

    ln_gate_kernel<<<NTOK, 256>>>(R, G, lng, lnb, Y);

    GemmCfg c2;
    c2.out[0] = (float*)d_out; c2.out[1] = nullptr; c2.out[2] = nullptr; c2.out[3] = nullptr;
    c2.bias[0] = bo; c2.bias[1] = nullptr; c2.bias[2] = nullptr; c2.bias[3] = nullptr;
    c2.act[0] = 0; c2.act[1] = 0; c2.act[2] = 0; c2.act[3] = 0;
    gemm_tc<<<dim3(8, 32), 256, GEMM_SMEM>>>(Y, Wot, c2);
}

// round 12
// speedup vs baseline: 5.2975x; 1.6215x over previous
#include <cuda_runtime.h>
#include <cuda_fp16.h>
#include <math.h>
#include <stdint.h>

#define NTOK 4096   // B*T
#define DM   1024
#define NH   16
#define DH   64
#define TT   2048
#define BB   2

// ---- fp16 gemm config ----
#define KTH   32            // k-tile (halfs)
#define NKTH  (DM/KTH)      // 32
#define SH    40            // padded k-stride (halfs)
#define GBUF  (128*SH)      // halfs per operand buffer = 5120
#define GEMM_SMEM (2*2*GBUF*2)   // 40960 B

// ---- retention smem: all tiles stride 72 halfs ----
#define RST   72
#define RBUF  (64*RST)      // 4608 halfs
// Qs(1) Ss(1) Ks(2) Vn(2) Vt(1) = 7 buffers
#define RET_SMEM (7*RBUF*2) // 64512 B

// Scratch (__device__ globals: allocation-free rule)
__device__ __half g_Qh[NTOK*DM];
__device__ __half g_Kh[NTOK*DM];
__device__ __half g_Vh[NTOK*DM];
__device__ __half g_Gh[NTOK*DM];
__device__ __half g_Xh[NTOK*DM];
__device__ __half g_Yh[NTOK*DM];
__device__ __half g_Wh4[4*DM*DM];   // Wq,Wk,Wv,Wg transposed K-major half
__device__ __half g_Woh[DM*DM];     // Wo transposed K-major half
__device__ float  g_R[NTOK*DM];

__device__ __forceinline__ uint32_t smem_u32(const void* p) {
    uint32_t a;
    asm("{ .reg .u64 t; cvta.to.shared.u64 t, %1; cvt.u32.u64 %0, t; }" : "=r"(a) : "l"(p));
    return a;
}
__device__ __forceinline__ uint32_t h2_u32(__half2 h) {
    union { __half2 h2; uint32_t u; } cvt; cvt.h2 = h; return cvt.u;
}
__device__ __forceinline__ void cpa16(uint32_t dst, const void* src) {
    asm volatile("cp.async.cg.shared.global [%0], [%1], 16;" :: "r"(dst), "l"(src) : "memory");
}
__device__ __forceinline__ void mma_f16(float* c, const uint32_t* a, const uint32_t* b) {
    asm volatile(
        "mma.sync.aligned.m16n8k16.row.col.f32.f16.f16.f32 "
        "{%0,%1,%2,%3}, {%4,%5,%6,%7}, {%8,%9}, {%0,%1,%2,%3};"
        : "+f"(c[0]), "+f"(c[1]), "+f"(c[2]), "+f"(c[3])
        : "r"(a[0]), "r"(a[1]), "r"(a[2]), "r"(a[3]), "r"(b[0]), "r"(b[1]));
}
__device__ __forceinline__ uint32_t ldsu32(const __half* p) { return *(const uint32_t*)p; }

struct GemmCfgH {
    void* out[4];
    const float* bias[4];
    int act[4];
};

// ---------------------------------------------------------------------------
// fp16 mma.sync GEMM: C tile 128x128 = A[M,1024] @ Bt[N,1024]^T
// A [m][k] half row-major; Bt [n][k] half K-major. 8 warps (2x4), warp 64x32.
// HOUT=1: store half; HOUT=0: store float.
// ---------------------------------------------------------------------------
template<int HOUT>
__global__ __launch_bounds__(256) void gemm_h(
    const __half* __restrict__ A, const __half* __restrict__ Bt, GemmCfgH cfg)
{
    extern __shared__ __align__(16) __half gsm[];
    __half* As[2] = { gsm,            gsm + 2*GBUF };
    __half* Bs[2] = { gsm + GBUF,     gsm + 3*GBUF };

    const int t = threadIdx.x;
    const int wid = t >> 5, lane = t & 31;
    const int wm = wid >> 2, wn = wid & 3;
    const int m0 = blockIdx.y * 128, n0 = blockIdx.x * 128;
    const int bsel = n0 >> 10;
    const int ncol0 = n0 & 1023;
    const int lq = lane >> 2, lr = lane & 3;

    const uint32_t sA0 = smem_u32(As[0]);
    const uint32_t sB0 = smem_u32(Bs[0]);
    const uint32_t bufStride = 2*GBUF*2;  // bytes

    float acc[4][4][4];
    #pragma unroll
    for (int i = 0; i < 4; i++)
        #pragma unroll
        for (int j = 0; j < 4; j++)
            #pragma unroll
            for (int q = 0; q < 4; q++) acc[i][j][q] = 0.f;

    auto loadTile = [&](int kt, int buf) {
        const int k0 = kt * KTH;
        #pragma unroll
        for (int i = 0; i < 2; i++) {
            int s = t + i * 256;
            int row = s >> 2, seg = s & 3;     // seg = 8 halfs (16B)
            cpa16(sA0 + buf * bufStride + (row * SH + seg * 8) * 2,
                  A + (size_t)(m0 + row) * DM + k0 + seg * 8);
            cpa16(sB0 + buf * bufStride + (row * SH + seg * 8) * 2,
                  Bt + (size_t)(n0 + row) * DM + k0 + seg * 8);
        }
        asm volatile("cp.async.commit_group;" ::: "memory");
    };

    loadTile(0, 0);

    for (int kt = 0; kt < NKTH; kt++) {
        if (kt + 1 < NKTH) {
            loadTile(kt + 1, (kt + 1) & 1);
            asm volatile("cp.async.wait_group 1;" ::: "memory");
        } else {
            asm volatile("cp.async.wait_group 0;" ::: "memory");
        }
        __syncthreads();

        const __half* a_s = As[kt & 1];
        const __half* b_s = Bs[kt & 1];

        #pragma unroll
        for (int ks = 0; ks < 2; ks++) {       // two k16 steps per KTH=32
            const int k0 = ks * 16;
            uint32_t af[4][4], bf[4][2];
            #pragma unroll
            for (int mi = 0; mi < 4; mi++) {
                const __half* ap = a_s + (wm * 64 + mi * 16 + lq) * SH + k0 + 2 * lr;
                af[mi][0] = ldsu32(ap);
                af[mi][1] = ldsu32(ap + 8 * SH);
                af[mi][2] = ldsu32(ap + 8);
                af[mi][3] = ldsu32(ap + 8 * SH + 8);
            }
            #pragma unroll
            for (int ni = 0; ni < 4; ni++) {
                const __half* bp = b_s + (wn * 32 + ni * 8 + lq) * SH + k0 + 2 * lr;
                bf[ni][0] = ldsu32(bp);
                bf[ni][1] = ldsu32(bp + 8);
            }
            #pragma unroll
            for (int mi = 0; mi < 4; mi++)
                #pragma unroll
                for (int ni = 0; ni < 4; ni++)
                    mma_f16(acc[mi][ni], af[mi], bf[ni]);
        }
        __syncthreads();
    }

    const float* bp = cfg.bias[bsel];
    const int act = cfg.act[bsel];

    #pragma unroll
    for (int mi = 0; mi < 4; mi++) {
        #pragma unroll
        for (int ni = 0; ni < 4; ni++) {
            const int col = ncol0 + wn * 32 + ni * 8 + lr * 2;
            float b0 = 0.f, b1 = 0.f;
            if (bp) { b0 = bp[col]; b1 = bp[col + 1]; }
            #pragma unroll
            for (int h = 0; h < 2; h++) {
                const int row = m0 + wm * 64 + mi * 16 + lq + h * 8;
                float z0 = acc[mi][ni][h * 2 + 0] + b0;
                float z1 = acc[mi][ni][h * 2 + 1] + b1;
                if (act) {
                    z0 = z0 / (1.0f + expf(-z0));
                    z1 = z1 / (1.0f + expf(-z1));
                }
                if (HOUT) {
                    *(__half2*)((__half*)cfg.out[bsel] + (size_t)row * DM + col) =
                        __floats2half2_rn(z0, z1);
                } else {
                    float2 v = make_float2(z0, z1);
                    *(float2*)((float*)cfg.out[bsel] + (size_t)row * DM + col) = v;
                }
            }
        }
    }
}

// ---------------------------------------------------------------------------
// Prep: X f32 -> half; 5 weights f32 -> half transposed K-major (one launch)
// ---------------------------------------------------------------------------
__global__ __launch_bounds__(256) void cvt_x(const float* __restrict__ in,
                                             __half* __restrict__ out)
{
    size_t i = ((size_t)blockIdx.x * 256 + threadIdx.x) * 8;
    float4 v0 = *(const float4*)(in + i);
    float4 v1 = *(const float4*)(in + i + 4);
    uint32_t o[4];
    o[0] = h2_u32(__floats2half2_rn(v0.x, v0.y));
    o[1] = h2_u32(__floats2half2_rn(v0.z, v0.w));
    o[2] = h2_u32(__floats2half2_rn(v1.x, v1.y));
    o[3] = h2_u32(__floats2half2_rn(v1.z, v1.w));
    *(uint4*)(out + i) = make_uint4(o[0], o[1], o[2], o[3]);
}

__global__ __launch_bounds__(256) void transpose_cvt5(
    const float* Wq, const float* Wk, const float* Wv, const float* Wg,
    const float* Wo, __half* Wh4, __half* Woh)
{
    __shared__ float tile[32][33];
    const int z = blockIdx.z;
    const float* W = (z == 0) ? Wq : (z == 1) ? Wk : (z == 2) ? Wv : (z == 3) ? Wg : Wo;
    __half* Wt = (z < 4) ? (Wh4 + (size_t)z * DM * DM) : Woh;
    const int k0 = blockIdx.x * 32, n0 = blockIdx.y * 32;
    const int tx = threadIdx.x & 31, ty = threadIdx.x >> 5;
    #pragma unroll
    for (int i = 0; i < 32; i += 8)
        tile[ty + i][tx] = W[(size_t)(k0 + ty + i) * DM + n0 + tx];
    __syncthreads();
    #pragma unroll
    for (int i = 0; i < 32; i += 8)
        Wt[(size_t)(n0 + ty + i) * DM + k0 + tx] = __float2half_rn(tile[tx][ty + i]);
}

// ---------------------------------------------------------------------------
// Retention fp16: per CTA 64 q-rows x (head,batch), work-descending decode.
// S = Q K^T (mma), decay+causal, S->half smem; O += S V via V^T smem transpose.
// ---------------------------------------------------------------------------
__global__ __launch_bounds__(256) void retention_h(
    const __half* __restrict__ Q, const __half* __restrict__ K,
    const __half* __restrict__ V, float* __restrict__ R)
{
    extern __shared__ __align__(16) __half rsm[];
    __half* Qs = rsm;                    // [64][72]
    __half* Ss = rsm + RBUF;             // [64][72]
    __half* Ks = rsm + 2*RBUF;           // 2 x [64][72]
    __half* Vn = rsm + 4*RBUF;           // 2 x [64][72]
    __half* Vt = rsm + 6*RBUF;           // [64][72]  (dh-major transposed)

    const int idx = blockIdx.x;
    const int qb = (TT/64 - 1) - (idx >> 5);
    const int rem = idx & 31;
    const int h = 15 - (rem >> 1);
    const int b = rem & 1;

    const int t = threadIdx.x;
    const int wid = t >> 5, lane = t & 31;
    const int wm = wid >> 1, wn = wid & 1;            // 4 x 2 warp grid
    const int lq = lane >> 2, lr = lane & 3;
    const size_t base = (size_t)b * TT * DM + (size_t)h * DH;
    const int t0 = qb * 64;

    const uint32_t sQ = smem_u32(Qs), sK = smem_u32(Ks), sV = smem_u32(Vn);

    // Q tile (64 rows x 64 halfs = 8 segs of 16B)
    #pragma unroll
    for (int i = 0; i < 2; i++) {
        int s = t + i * 256;
        int row = s >> 3, seg = s & 7;
        cpa16(sQ + (row * RST + seg * 8) * 2,
              Q + base + (size_t)(t0 + row) * DM + seg * 8);
    }
    asm volatile("cp.async.commit_group;" ::: "memory");

    const float gamma = 1.0f - exp2f(-(float)(5 + h));
    const float l2g   = log2f(gamma);
    float diffmax = 24.0f / (-l2g);
    int nb_back = (diffmax > 1.0e8f) ? qb : ((int)(diffmax * (1.0f / 64.0f)) + 2);
    int sb0 = qb - nb_back; if (sb0 < 0) sb0 = 0;
    const int nit = qb - sb0 + 1;

    float rowf[2], colf[8];
    #pragma unroll
    for (int i = 0; i < 2; i++)
        rowf[i] = exp2f(l2g * (float)(wm * 16 + lq + 8 * i)) * 0.125f;
    #pragma unroll
    for (int ni = 0; ni < 4; ni++)
        #pragma unroll
        for (int j = 0; j < 2; j++)
            colf[ni * 2 + j] = exp2f(-l2g * (float)(wn * 32 + ni * 8 + 2 * lr + j));

    auto loadKV = [&](int sb, int buf) {
        #pragma unroll
        for (int i = 0; i < 2; i++) {
            int s = t + i * 256;
            int row = s >> 3, seg = s & 7;
            cpa16(sK + (buf * RBUF + row * RST + seg * 8) * 2,
                  K + base + (size_t)(sb * 64 + row) * DM + seg * 8);
            cpa16(sV + (buf * RBUF + row * RST + seg * 8) * 2,
                  V + base + (size_t)(sb * 64 + row) * DM + seg * 8);
        }
        asm volatile("cp.async.commit_group;" ::: "memory");
    };

    loadKV(sb0, 0);

    float oacc[4][4];
    #pragma unroll
    for (int ni = 0; ni < 4; ni++)
        #pragma unroll
        for (int q = 0; q < 4; q++) oacc[ni][q] = 0.f;

    // transpose lane mapping: dp = lane&3 (d-pairs), rp = lane>>2 (r-pairs)
    const int tdp = lane & 3, trp = lane >> 2;

    for (int it = 0; it < nit; it++) {
        const int sb = sb0 + it;
        const int buf = it & 1;
        asm volatile("cp.async.wait_group 0;" ::: "memory");
        __syncthreads();

        // ---- S = Q K^T ----
        float sacc[4][4];
        #pragma unroll
        for (int ni = 0; ni < 4; ni++)
            #pragma unroll
            for (int q = 0; q < 4; q++) sacc[ni][q] = 0.f;

        const __half* kbuf = Ks + buf * RBUF;
        #pragma unroll
        for (int ks = 0; ks < 4; ks++) {              // dh = 64 = 4 x k16
            const int k0 = ks * 16;
            uint32_t af[4];
            const __half* ap = Qs + (wm * 16 + lq) * RST + k0 + 2 * lr;
            af[0] = ldsu32(ap);
            af[1] = ldsu32(ap + 8 * RST);
            af[2] = ldsu32(ap + 8);
            af[3] = ldsu32(ap + 8 * RST + 8);
            #pragma unroll
            for (int ni = 0; ni < 4; ni++) {
                const __half* bp = kbuf + (wn * 32 + ni * 8 + lq) * RST + k0 + 2 * lr;
                uint32_t bf[2] = { ldsu32(bp), ldsu32(bp + 8) };
                mma_f16(sacc[ni], af, bf);
            }
        }

        if (it + 1 < nit) loadKV(sb + 1, (it + 1) & 1);
        else asm volatile("cp.async.commit_group;" ::: "memory");

        // ---- decay + causal, convert to half, store S ----
        const float pb = exp2f(l2g * (float)(64 * (qb - sb)));
        const bool diag = (sb == qb);
        #pragma unroll
        for (int ni = 0; ni < 4; ni++) {
            const int nl0 = wn * 32 + ni * 8 + 2 * lr;
            #pragma unroll
            for (int half_ = 0; half_ < 2; half_++) {
                const int mloc = wm * 16 + lq + half_ * 8;
                const float wr = rowf[half_] * pb;
                float v0 = sacc[ni][half_ * 2 + 0] * (wr * colf[ni * 2 + 0]);
                float v1 = sacc[ni][half_ * 2 + 1] * (wr * colf[ni * 2 + 1]);
                if (diag && nl0     > mloc) v0 = 0.f;
                if (diag && nl0 + 1 > mloc) v1 = 0.f;
                *(__half2*)&Ss[mloc * RST + nl0] = __floats2half2_rn(v0, v1);
            }
        }

        // ---- transpose Vn[buf] -> Vt (half2-pair, conflict-free mapping) ----
        {
            const __half* vsrc = Vn + buf * RBUF;
            const int d = 2 * (tdp + 4 * wid);        // 0..62 even
            #pragma unroll
            for (int ir = 0; ir < 4; ir++) {
                const int r = 2 * (trp + 8 * ir);     // 0..62 even
                uint32_t v0 = ldsu32(vsrc + r * RST + d);
                uint32_t v1 = ldsu32(vsrc + (r + 1) * RST + d);
                *(uint32_t*)&Vt[d * RST + r]       = __byte_perm(v0, v1, 0x5410);
                *(uint32_t*)&Vt[(d + 1) * RST + r] = __byte_perm(v0, v1, 0x7632);
            }
        }
        __syncthreads();

        // ---- O += S V  (A = S[m][tok], B = Vt[dh][tok]) ----
        #pragma unroll
        for (int ks = 0; ks < 4; ks++) {              // tok = 64 = 4 x k16
            const int k0 = ks * 16;
            uint32_t af[4];
            const __half* ap = Ss + (wm * 16 + lq) * RST + k0 + 2 * lr;
            af[0] = ldsu32(ap);
            af[1] = ldsu32(ap + 8 * RST);
            af[2] = ldsu32(ap + 8);
            af[3] = ldsu32(ap + 8 * RST + 8);
            #pragma unroll
            for (int ni = 0; ni < 4; ni++) {
                const __half* bpv = Vt + (wn * 32 + ni * 8 + lq) * RST + k0 + 2 * lr;
                uint32_t bf[2] = { ldsu32(bpv), ldsu32(bpv + 8) };
                mma_f16(oacc[ni], af, bf);
            }
        }
        __syncthreads();
    }

    #pragma unroll
    for (int ni = 0; ni < 4; ni++) {
        const int col = wn * 32 + ni * 8 + 2 * lr;
        #pragma unroll
        for (int half_ = 0; half_ < 2; half_++) {
            const int row = t0 + wm * 16 + lq + half_ * 8;
            float2 v = make_float2(oacc[ni][half_ * 2 + 0], oacc[ni][half_ * 2 + 1]);
            *(float2*)(R + base + (size_t)row * DM + col) = v;
        }
    }
}

// ---------------------------------------------------------------------------
// LayerNorm * gate: R f32, G half -> Y half
// ---------------------------------------------------------------------------
__global__ __launch_bounds__(256) void ln_gate_h(
    const float* __restrict__ R, const __half* __restrict__ G,
    const float* __restrict__ lng, const float* __restrict__ lnb,
    __half* __restrict__ Y)
{
    __shared__ float red[8];
    const int row = blockIdx.x;
    const int t = threadIdx.x;
    const size_t off = (size_t)row * DM + t * 4;

    float4 x = *(const float4*)(R + off);

    float s = x.x + x.y + x.z + x.w;
    #pragma unroll
    for (int o = 16; o > 0; o >>= 1) s += __shfl_xor_sync(0xffffffffu, s, o);
    if ((t & 31) == 0) red[t >> 5] = s;
    __syncthreads();
    float tot = red[0] + red[1] + red[2] + red[3] + red[4] + red[5] + red[6] + red[7];
    const float mu = tot * (1.0f / 1024.0f);

    float d0 = x.x - mu, d1 = x.y - mu, d2 = x.z - mu, d3 = x.w - mu;
    float sq = d0 * d0 + d1 * d1 + d2 * d2 + d3 * d3;
    #pragma unroll
    for (int o = 16; o > 0; o >>= 1) sq += __shfl_xor_sync(0xffffffffu, sq, o);
    __syncthreads();
    if ((t & 31) == 0) red[t >> 5] = sq;
    __syncthreads();
    float totsq = red[0] + red[1] + red[2] + red[3] + red[4] + red[5] + red[6] + red[7];
    const float rstd = rsqrtf(totsq * (1.0f / 1024.0f) + 1e-3f);

    float4 g4 = *(const float4*)(lng + t * 4);
    float4 b4 = *(const float4*)(lnb + t * 4);
    uint2 gu = *(const uint2*)(G + off);
    float2 ga = __half22float2(*(__half2*)&gu.x);
    float2 gb = __half22float2(*(__half2*)&gu.y);

    __half2 y0 = __floats2half2_rn((d0 * rstd * g4.x + b4.x) * ga.x,
                                   (d1 * rstd * g4.y + b4.y) * ga.y);
    __half2 y1 = __floats2half2_rn((d2 * rstd * g4.z + b4.z) * gb.x,
                                   (d3 * rstd * g4.w + b4.w) * gb.y);
    __half2* yp = (__half2*)(Y + off);
    yp[0] = y0;
    yp[1] = y1;
}

// ---------------------------------------------------------------------------
extern "C" void kernel_launch(void* const* d_in, const int* in_sizes, int n_in,
                              void* d_out, int out_size)
{
    const float* x   = (const float*)d_in[0];
    const float* Wq  = (const float*)d_in[1];
    const float* Wk  = (const float*)d_in[2];
    const float* Wv  = (const float*)d_in[3];
    const float* Wg  = (const float*)d_in[4];
    const float* bg  = (const float*)d_in[5];
    const float* Wo  = (const float*)d_in[6];
    const float* bo  = (const float*)d_in[7];
    const float* lng = (const float*)d_in[8];
    const float* lnb = (const float*)d_in[9];

    __half *Qh, *Kh, *Vh, *Gh, *Xh, *Yh, *Wh4, *Woh;
    float *R;
    cudaGetSymbolAddress((void**)&Qh,  g_Qh);
    cudaGetSymbolAddress((void**)&Kh,  g_Kh);
    cudaGetSymbolAddress((void**)&Vh,  g_Vh);
    cudaGetSymbolAddress((void**)&Gh,  g_Gh);
    cudaGetSymbolAddress((void**)&Xh,  g_Xh);
    cudaGetSymbolAddress((void**)&Yh,  g_Yh);
    cudaGetSymbolAddress((void**)&Wh4, g_Wh4);
    cudaGetSymbolAddress((void**)&Woh, g_Woh);
    cudaGetSymbolAddress((void**)&R,   g_R);

    cvt_x<<<(NTOK * DM) / (256 * 8), 256>>>(x, Xh);
    transpose_cvt5<<<dim3(32, 32, 5), 256>>>(Wq, Wk, Wv, Wg, Wo, Wh4, Woh);

    // Fused QKVG projection (N = 4096), half outputs
    GemmCfgH c1;
    c1.out[0] = Qh; c1.out[1] = Kh; c1.out[2] = Vh; c1.out[3] = Gh;
    c1.bias[0] = nullptr; c1.bias[1] = nullptr; c1.bias[2] = nullptr; c1.bias[3] = bg;
    c1.act[0] = 0; c1.act[1] = 0; c1.act[2] = 0; c1.act[3] = 1;
    gemm_h<1><<<dim3(32, 32), 256, GEMM_SMEM>>>(Xh, Wh4, c1);

    cudaFuncSetAttribute(retention_h, cudaFuncAttributeMaxDynamicSharedMemorySize, RET_SMEM);
    retention_h<<<dim3((TT/64) * NH * BB), 256, RET_SMEM>>>(Qh, Kh, Vh, R);

    ln_gate_h<<<NTOK, 256>>>(R, Gh, lng, lnb, Yh);

    // Output projection, f32 out
    GemmCfgH c2;
    c2.out[0] = d_out; c2.out[1] = nullptr; c2.out[2] = nullptr; c2.out[3] = nullptr;
    c2.bias[0] = bo; c2.bias[1] = nullptr; c2.bias[2] = nullptr; c2.bias[3] = nullptr;
    c2.act[0] = 0; c2.act[1] = 0; c2.act[2] = 0; c2.act[3] = 0;
    gemm_h<0><<<dim3(8, 32), 256, GEMM_SMEM>>>(Yh, Woh, c2);
}

// round 13
// speedup vs baseline: 6.5010x; 1.2272x over previous
#include <cuda_runtime.h>
#include <cuda_fp16.h>
#include <math.h>
#include <stdint.h>

#define NTOK 4096   // B*T
#define DM   1024
#define NH   16
#define DH   64
#define TT   2048
#define BB   2

// ---- fp16 gemm config ----
#define KTH   32            // k-tile (halfs)
#define NKTH  (DM/KTH)      // 32
#define SH    40            // padded k-stride (halfs); 20 words/row = bank-perm
#define GBUF  (128*SH)      // halfs per operand buffer
#define GEMM_SMEM (2*2*GBUF*2)   // 40960 B

// ---- retention smem: stride 72 halfs (36 words/row = bank-perm) ----
#define RST   72
#define RBUF  (64*RST)
// Qs(1) Ss(1) Ks(2) Vn(2) = 6 buffers  (Vt eliminated via ldmatrix.trans)
#define RET_SMEM (6*RBUF*2) // 55296 B

// Scratch (__device__ globals: allocation-free rule)
__device__ __half g_Qh[NTOK*DM];
__device__ __half g_Kh[NTOK*DM];
__device__ __half g_Vh[NTOK*DM];
__device__ __half g_Gh[NTOK*DM];
__device__ __half g_Xh[NTOK*DM];
__device__ __half g_Yh[NTOK*DM];
__device__ __half g_Wh4[4*DM*DM];
__device__ __half g_Woh[DM*DM];
__device__ float  g_R[NTOK*DM];

__device__ __forceinline__ uint32_t smem_u32(const void* p) {
    uint32_t a;
    asm("{ .reg .u64 t; cvta.to.shared.u64 t, %1; cvt.u32.u64 %0, t; }" : "=r"(a) : "l"(p));
    return a;
}
__device__ __forceinline__ uint32_t h2_u32(__half2 h) {
    union { __half2 h2; uint32_t u; } cvt; cvt.h2 = h; return cvt.u;
}
__device__ __forceinline__ void cpa16(uint32_t dst, const void* src) {
    asm volatile("cp.async.cg.shared.global [%0], [%1], 16;" :: "r"(dst), "l"(src) : "memory");
}
__device__ __forceinline__ void mma_f16(float* c, const uint32_t* a, const uint32_t* b) {
    asm volatile(
        "mma.sync.aligned.m16n8k16.row.col.f32.f16.f16.f32 "
        "{%0,%1,%2,%3}, {%4,%5,%6,%7}, {%8,%9}, {%0,%1,%2,%3};"
        : "+f"(c[0]), "+f"(c[1]), "+f"(c[2]), "+f"(c[3])
        : "r"(a[0]), "r"(a[1]), "r"(a[2]), "r"(a[3]), "r"(b[0]), "r"(b[1]));
}
__device__ __forceinline__ void ldsm_x4(uint32_t* r, uint32_t a) {
    asm volatile("ldmatrix.sync.aligned.m8n8.x4.shared.b16 {%0,%1,%2,%3}, [%4];"
        : "=r"(r[0]), "=r"(r[1]), "=r"(r[2]), "=r"(r[3]) : "r"(a));
}
__device__ __forceinline__ void ldsm_x4t(uint32_t* r, uint32_t a) {
    asm volatile("ldmatrix.sync.aligned.m8n8.x4.trans.shared.b16 {%0,%1,%2,%3}, [%4];"
        : "=r"(r[0]), "=r"(r[1]), "=r"(r[2]), "=r"(r[3]) : "r"(a));
}

struct GemmCfgH {
    void* out[4];
    const float* bias[4];
    int act[4];
};

// ---------------------------------------------------------------------------
// fp16 mma.sync GEMM with ldmatrix fragment loads.
// C tile 128x128 = A[M,1024] @ Bt[N,1024]^T. 8 warps (2x4), warp 64x32.
// ---------------------------------------------------------------------------
template<int HOUT>
__global__ __launch_bounds__(256) void gemm_h(
    const __half* __restrict__ A, const __half* __restrict__ Bt, GemmCfgH cfg)
{
    extern __shared__ __align__(16) __half gsm[];
    const int t = threadIdx.x;
    const int wid = t >> 5, lane = t & 31;
    const int wm = wid >> 2, wn = wid & 3;
    const int m0 = blockIdx.y * 128, n0 = blockIdx.x * 128;
    const int bsel = n0 >> 10;
    const int ncol0 = n0 & 1023;
    const int lq = lane >> 2, lr = lane & 3;

    const uint32_t sA0 = smem_u32(gsm);
    const uint32_t sB0 = sA0 + GBUF * 2;
    const uint32_t bufStride = 2 * GBUF * 2;  // bytes

    // ldmatrix per-lane offsets (bytes)
    const int l15 = lane & 15;
    const int k8a = (lane & 16) ? 8 : 0;
    const uint32_t aoff = ((wm * 64 + l15) * SH + k8a) * 2;
    const uint32_t boff = ((wn * 32 + (lane & 7) + k8a) * SH + ((lane & 8) ? 8 : 0)) * 2;

    float acc[4][4][4];
    #pragma unroll
    for (int i = 0; i < 4; i++)
        #pragma unroll
        for (int j = 0; j < 4; j++)
            #pragma unroll
            for (int q = 0; q < 4; q++) acc[i][j][q] = 0.f;

    auto loadTile = [&](int kt, int buf) {
        const int k0 = kt * KTH;
        #pragma unroll
        for (int i = 0; i < 2; i++) {
            int s = t + i * 256;
            int row = s >> 2, seg = s & 3;
            cpa16(sA0 + buf * bufStride + (row * SH + seg * 8) * 2,
                  A + (size_t)(m0 + row) * DM + k0 + seg * 8);
            cpa16(sB0 + buf * bufStride + (row * SH + seg * 8) * 2,
                  Bt + (size_t)(n0 + row) * DM + k0 + seg * 8);
        }
        asm volatile("cp.async.commit_group;" ::: "memory");
    };

    loadTile(0, 0);

    for (int kt = 0; kt < NKTH; kt++) {
        if (kt + 1 < NKTH) {
            loadTile(kt + 1, (kt + 1) & 1);
            asm volatile("cp.async.wait_group 1;" ::: "memory");
        } else {
            asm volatile("cp.async.wait_group 0;" ::: "memory");
        }
        __syncthreads();

        const uint32_t aB = sA0 + (kt & 1) * bufStride;
        const uint32_t bB = sB0 + (kt & 1) * bufStride;

        #pragma unroll
        for (int ks = 0; ks < 2; ks++) {
            const uint32_t kb = ks * 32;   // 16 halfs
            uint32_t af[4][4], b01[4], b23[4];
            #pragma unroll
            for (int mi = 0; mi < 4; mi++)
                ldsm_x4(af[mi], aB + aoff + mi * (16 * SH * 2) + kb);
            ldsm_x4(b01, bB + boff + kb);
            ldsm_x4(b23, bB + boff + 16 * SH * 2 + kb);
            #pragma unroll
            for (int mi = 0; mi < 4; mi++) {
                mma_f16(acc[mi][0], af[mi], b01 + 0);
                mma_f16(acc[mi][1], af[mi], b01 + 2);
                mma_f16(acc[mi][2], af[mi], b23 + 0);
                mma_f16(acc[mi][3], af[mi], b23 + 2);
            }
        }
        __syncthreads();
    }

    const float* bp = cfg.bias[bsel];
    const int act = cfg.act[bsel];

    #pragma unroll
    for (int mi = 0; mi < 4; mi++) {
        #pragma unroll
        for (int ni = 0; ni < 4; ni++) {
            const int col = ncol0 + wn * 32 + ni * 8 + lr * 2;
            float b0 = 0.f, b1 = 0.f;
            if (bp) { b0 = bp[col]; b1 = bp[col + 1]; }
            #pragma unroll
            for (int h = 0; h < 2; h++) {
                const int row = m0 + wm * 64 + mi * 16 + lq + h * 8;
                float z0 = acc[mi][ni][h * 2 + 0] + b0;
                float z1 = acc[mi][ni][h * 2 + 1] + b1;
                if (act) {
                    z0 = z0 / (1.0f + expf(-z0));
                    z1 = z1 / (1.0f + expf(-z1));
                }
                if (HOUT) {
                    *(__half2*)((__half*)cfg.out[bsel] + (size_t)row * DM + col) =
                        __floats2half2_rn(z0, z1);
                } else {
                    float2 v = make_float2(z0, z1);
                    *(float2*)((float*)cfg.out[bsel] + (size_t)row * DM + col) = v;
                }
            }
        }
    }
}

// ---------------------------------------------------------------------------
// Prep
// ---------------------------------------------------------------------------
__global__ __launch_bounds__(256) void cvt_x(const float* __restrict__ in,
                                             __half* __restrict__ out)
{
    size_t i = ((size_t)blockIdx.x * 256 + threadIdx.x) * 8;
    float4 v0 = *(const float4*)(in + i);
    float4 v1 = *(const float4*)(in + i + 4);
    uint32_t o[4];
    o[0] = h2_u32(__floats2half2_rn(v0.x, v0.y));
    o[1] = h2_u32(__floats2half2_rn(v0.z, v0.w));
    o[2] = h2_u32(__floats2half2_rn(v1.x, v1.y));
    o[3] = h2_u32(__floats2half2_rn(v1.z, v1.w));
    *(uint4*)(out + i) = make_uint4(o[0], o[1], o[2], o[3]);
}

__global__ __launch_bounds__(256) void transpose_cvt5(
    const float* Wq, const float* Wk, const float* Wv, const float* Wg,
    const float* Wo, __half* Wh4, __half* Woh)
{
    __shared__ float tile[32][33];
    const int z = blockIdx.z;
    const float* W = (z == 0) ? Wq : (z == 1) ? Wk : (z == 2) ? Wv : (z == 3) ? Wg : Wo;
    __half* Wt = (z < 4) ? (Wh4 + (size_t)z * DM * DM) : Woh;
    const int k0 = blockIdx.x * 32, n0 = blockIdx.y * 32;
    const int tx = threadIdx.x & 31, ty = threadIdx.x >> 5;
    #pragma unroll
    for (int i = 0; i < 32; i += 8)
        tile[ty + i][tx] = W[(size_t)(k0 + ty + i) * DM + n0 + tx];
    __syncthreads();
    #pragma unroll
    for (int i = 0; i < 32; i += 8)
        Wt[(size_t)(n0 + ty + i) * DM + k0 + tx] = __float2half_rn(tile[tx][ty + i]);
}

// ---------------------------------------------------------------------------
// Retention fp16 + ldmatrix. O-gemm B loaded straight from natural-layout V
// via ldmatrix.trans (no in-SMEM transpose). Work-descending flat grid.
// ---------------------------------------------------------------------------
__global__ __launch_bounds__(256) void retention_h(
    const __half* __restrict__ Q, const __half* __restrict__ K,
    const __half* __restrict__ V, float* __restrict__ R)
{
    extern __shared__ __align__(16) __half rsm[];
    const uint32_t sQ = smem_u32(rsm);
    const uint32_t sS = sQ + RBUF * 2;
    const uint32_t sK = sS + RBUF * 2;       // 2 buffers
    const uint32_t sV = sK + 2 * RBUF * 2;   // 2 buffers
    __half* Ss = rsm + RBUF;

    const int idx = blockIdx.x;
    const int qb = (TT/64 - 1) - (idx >> 5);
    const int rem = idx & 31;
    const int h = 15 - (rem >> 1);
    const int b = rem & 1;

    const int t = threadIdx.x;
    const int wid = t >> 5, lane = t & 31;
    const int wm = wid >> 1, wn = wid & 1;            // 4 x 2 warp grid
    const int lq = lane >> 2, lr = lane & 3;
    const size_t base = (size_t)b * TT * DM + (size_t)h * DH;
    const int t0 = qb * 64;

    // ldmatrix per-lane offsets (bytes)
    const int l15 = lane & 15;
    const int k8a = (lane & 16) ? 8 : 0;
    const uint32_t qoff  = ((wm * 16 + l15) * RST + k8a) * 2;                    // A (Qs/Ss)
    const uint32_t koffB = ((wn * 32 + (lane & 7) + k8a) * RST + ((lane & 8) ? 8 : 0)) * 2; // B (Ks)
    const uint32_t voffB = (l15 * RST + wn * 32 + k8a) * 2;                      // B (Vn, trans)

    // Q tile
    #pragma unroll
    for (int i = 0; i < 2; i++) {
        int s = t + i * 256;
        int row = s >> 3, seg = s & 7;
        cpa16(sQ + (row * RST + seg * 8) * 2,
              Q + base + (size_t)(t0 + row) * DM + seg * 8);
    }
    asm volatile("cp.async.commit_group;" ::: "memory");

    const float gamma = 1.0f - exp2f(-(float)(5 + h));
    const float l2g   = log2f(gamma);
    float diffmax = 24.0f / (-l2g);
    int nb_back = (diffmax > 1.0e8f) ? qb : ((int)(diffmax * (1.0f / 64.0f)) + 2);
    int sb0 = qb - nb_back; if (sb0 < 0) sb0 = 0;
    const int nit = qb - sb0 + 1;

    float rowf[2], colf[8];
    #pragma unroll
    for (int i = 0; i < 2; i++)
        rowf[i] = exp2f(l2g * (float)(wm * 16 + lq + 8 * i)) * 0.125f;
    #pragma unroll
    for (int ni = 0; ni < 4; ni++)
        #pragma unroll
        for (int j = 0; j < 2; j++)
            colf[ni * 2 + j] = exp2f(-l2g * (float)(wn * 32 + ni * 8 + 2 * lr + j));

    auto loadKV = [&](int sb, int buf) {
        #pragma unroll
        for (int i = 0; i < 2; i++) {
            int s = t + i * 256;
            int row = s >> 3, seg = s & 7;
            cpa16(sK + (buf * RBUF + row * RST + seg * 8) * 2,
                  K + base + (size_t)(sb * 64 + row) * DM + seg * 8);
            cpa16(sV + (buf * RBUF + row * RST + seg * 8) * 2,
                  V + base + (size_t)(sb * 64 + row) * DM + seg * 8);
        }
        asm volatile("cp.async.commit_group;" ::: "memory");
    };

    loadKV(sb0, 0);

    float oacc[4][4];
    #pragma unroll
    for (int ni = 0; ni < 4; ni++)
        #pragma unroll
        for (int q = 0; q < 4; q++) oacc[ni][q] = 0.f;

    for (int it = 0; it < nit; it++) {
        const int sb = sb0 + it;
        const int buf = it & 1;
        asm volatile("cp.async.wait_group 0;" ::: "memory");
        __syncthreads();

        // ---- S = Q K^T ----
        float sacc[4][4];
        #pragma unroll
        for (int ni = 0; ni < 4; ni++)
            #pragma unroll
            for (int q = 0; q < 4; q++) sacc[ni][q] = 0.f;

        const uint32_t kB = sK + buf * RBUF * 2;
        #pragma unroll
        for (int ks = 0; ks < 4; ks++) {
            const uint32_t kb = ks * 32;
            uint32_t af[4], b01[4], b23[4];
            ldsm_x4(af, sQ + qoff + kb);
            ldsm_x4(b01, kB + koffB + kb);
            ldsm_x4(b23, kB + koffB + 16 * RST * 2 + kb);
            mma_f16(sacc[0], af, b01 + 0);
            mma_f16(sacc[1], af, b01 + 2);
            mma_f16(sacc[2], af, b23 + 0);
            mma_f16(sacc[3], af, b23 + 2);
        }

        if (it + 1 < nit) loadKV(sb + 1, (it + 1) & 1);
        else asm volatile("cp.async.commit_group;" ::: "memory");

        // ---- decay + causal, convert to half, store S ----
        const float pb = exp2f(l2g * (float)(64 * (qb - sb)));
        const bool diag = (sb == qb);
        #pragma unroll
        for (int ni = 0; ni < 4; ni++) {
            const int nl0 = wn * 32 + ni * 8 + 2 * lr;
            #pragma unroll
            for (int half_ = 0; half_ < 2; half_++) {
                const int mloc = wm * 16 + lq + half_ * 8;
                const float wr = rowf[half_] * pb;
                float v0 = sacc[ni][half_ * 2 + 0] * (wr * colf[ni * 2 + 0]);
                float v1 = sacc[ni][half_ * 2 + 1] * (wr * colf[ni * 2 + 1]);
                if (diag && nl0     > mloc) v0 = 0.f;
                if (diag && nl0 + 1 > mloc) v1 = 0.f;
                *(__half2*)&Ss[mloc * RST + nl0] = __floats2half2_rn(v0, v1);
            }
        }
        __syncthreads();

        // ---- O += S V  (B loaded transposed from natural-layout Vn) ----
        const uint32_t vB = sV + buf * RBUF * 2;
        #pragma unroll
        for (int ks = 0; ks < 4; ks++) {
            const uint32_t tokb = ks * 16 * RST * 2;
            uint32_t af[4], b01[4], b23[4];
            ldsm_x4(af, sS + qoff + ks * 32);
            ldsm_x4t(b01, vB + voffB + tokb);
            ldsm_x4t(b23, vB + voffB + 16 * 2 + tokb);
            mma_f16(oacc[0], af, b01 + 0);
            mma_f16(oacc[1], af, b01 + 2);
            mma_f16(oacc[2], af, b23 + 0);
            mma_f16(oacc[3], af, b23 + 2);
        }
    }

    #pragma unroll
    for (int ni = 0; ni < 4; ni++) {
        const int col = wn * 32 + ni * 8 + 2 * lr;
        #pragma unroll
        for (int half_ = 0; half_ < 2; half_++) {
            const int row = t0 + wm * 16 + lq + half_ * 8;
            float2 v = make_float2(oacc[ni][half_ * 2 + 0], oacc[ni][half_ * 2 + 1]);
            *(float2*)(R + base + (size_t)row * DM + col) = v;
        }
    }
}

// ---------------------------------------------------------------------------
// LayerNorm * gate: R f32, G half -> Y half
// ---------------------------------------------------------------------------
__global__ __launch_bounds__(256) void ln_gate_h(
    const float* __restrict__ R, const __half* __restrict__ G,
    const float* __restrict__ lng, const float* __restrict__ lnb,
    __half* __restrict__ Y)
{
    __shared__ float red[8];
    const int row = blockIdx.x;
    const int t = threadIdx.x;
    const size_t off = (size_t)row * DM + t * 4;

    float4 x = *(const float4*)(R + off);

    float s = x.x + x.y + x.z + x.w;
    #pragma unroll
    for (int o = 16; o > 0; o >>= 1) s += __shfl_xor_sync(0xffffffffu, s, o);
    if ((t & 31) == 0) red[t >> 5] = s;
    __syncthreads();
    float tot = red[0] + red[1] + red[2] + red[3] + red[4] + red[5] + red[6] + red[7];
    const float mu = tot * (1.0f / 1024.0f);

    float d0 = x.x - mu, d1 = x.y - mu, d2 = x.z - mu, d3 = x.w - mu;
    float sq = d0 * d0 + d1 * d1 + d2 * d2 + d3 * d3;
    #pragma unroll
    for (int o = 16; o > 0; o >>= 1) sq += __shfl_xor_sync(0xffffffffu, sq, o);
    __syncthreads();
    if ((t & 31) == 0) red[t >> 5] = sq;
    __syncthreads();
    float totsq = red[0] + red[1] + red[2] + red[3] + red[4] + red[5] + red[6] + red[7];
    const float rstd = rsqrtf(totsq * (1.0f / 1024.0f) + 1e-3f);

    float4 g4 = *(const float4*)(lng + t * 4);
    float4 b4 = *(const float4*)(lnb + t * 4);
    uint2 gu = *(const uint2*)(G + off);
    float2 ga = __half22float2(*(__half2*)&gu.x);
    float2 gb = __half22float2(*(__half2*)&gu.y);

    __half2 y0 = __floats2half2_rn((d0 * rstd * g4.x + b4.x) * ga.x,
                                   (d1 * rstd * g4.y + b4.y) * ga.y);
    __half2 y1 = __floats2half2_rn((d2 * rstd * g4.z + b4.z) * gb.x,
                                   (d3 * rstd * g4.w + b4.w) * gb.y);
    __half2* yp = (__half2*)(Y + off);
    yp[0] = y0;
    yp[1] = y1;
}

// ---------------------------------------------------------------------------
extern "C" void kernel_launch(void* const* d_in, const int* in_sizes, int n_in,
                              void* d_out, int out_size)
{
    const float* x   = (const float*)d_in[0];
    const float* Wq  = (const float*)d_in[1];
    const float* Wk  = (const float*)d_in[2];
    const float* Wv  = (const float*)d_in[3];
    const float* Wg  = (const float*)d_in[4];
    const float* bg  = (const float*)d_in[5];
    const float* Wo  = (const float*)d_in[6];
    const float* bo  = (const float*)d_in[7];
    const float* lng = (const float*)d_in[8];
    const float* lnb = (const float*)d_in[9];

    __half *Qh, *Kh, *Vh, *Gh, *Xh, *Yh, *Wh4, *Woh;
    float *R;
    cudaGetSymbolAddress((void**)&Qh,  g_Qh);
    cudaGetSymbolAddress((void**)&Kh,  g_Kh);
    cudaGetSymbolAddress((void**)&Vh,  g_Vh);
    cudaGetSymbolAddress((void**)&Gh,  g_Gh);
    cudaGetSymbolAddress((void**)&Xh,  g_Xh);
    cudaGetSymbolAddress((void**)&Yh,  g_Yh);
    cudaGetSymbolAddress((void**)&Wh4, g_Wh4);
    cudaGetSymbolAddress((void**)&Woh, g_Woh);
    cudaGetSymbolAddress((void**)&R,   g_R);

    cvt_x<<<(NTOK * DM) / (256 * 8), 256>>>(x, Xh);
    transpose_cvt5<<<dim3(32, 32, 5), 256>>>(Wq, Wk, Wv, Wg, Wo, Wh4, Woh);

    GemmCfgH c1;
    c1.out[0] = Qh; c1.out[1] = Kh; c1.out[2] = Vh; c1.out[3] = Gh;
    c1.bias[0] = nullptr; c1.bias[1] = nullptr; c1.bias[2] = nullptr; c1.bias[3] = bg;
    c1.act[0] = 0; c1.act[1] = 0; c1.act[2] = 0; c1.act[3] = 1;
    gemm_h<1><<<dim3(32, 32), 256, GEMM_SMEM>>>(Xh, Wh4, c1);

    cudaFuncSetAttribute(retention_h, cudaFuncAttributeMaxDynamicSharedMemorySize, RET_SMEM);
    retention_h<<<dim3((TT/64) * NH * BB), 256, RET_SMEM>>>(Qh, Kh, Vh, R);

    ln_gate_h<<<NTOK, 256>>>(R, Gh, lng, lnb, Yh);

    GemmCfgH c2;
    c2.out[0] = d_out; c2.out[1] = nullptr; c2.out[2] = nullptr; c2.out[3] = nullptr;
    c2.bias[0] = bo; c2.bias[1] = nullptr; c2.bias[2] = nullptr; c2.bias[3] = nullptr;
    c2.act[0] = 0; c2.act[1] = 0; c2.act[2] = 0; c2.act[3] = 0;
    gemm_h<0><<<dim3(8, 32), 256, GEMM_SMEM>>>(Yh, Woh, c2);
}

// round 14
// speedup vs baseline: 6.6339x; 1.0204x over previous
#include <cuda_runtime.h>
#include <cuda_fp16.h>
#include <math.h>
#include <stdint.h>

#define NTOK 4096   // B*T
#define DM   1024
#define NH   16
#define DH   64
#define TT   2048
#define BB   2

// ---- fp16 gemm config ----
#define KTH   32            // k-tile (halfs)
#define NKTH  (DM/KTH)      // 32
#define SH    40            // padded k-stride (halfs)
#define GBUF  (128*SH)
#define GEMM_SMEM (2*2*GBUF*2)   // 40960 B

// ---- retention smem: stride 72 halfs ----
#define RST   72
#define RBUF  (64*RST)
// Qs(1) Ks(2) Vn(2) = 5 buffers (Ss eliminated: S stays in registers)
#define RET_SMEM (5*RBUF*2) // 46080 B

// Scratch (__device__ globals: allocation-free rule)
__device__ __half g_Qh[NTOK*DM];
__device__ __half g_Kh[NTOK*DM];
__device__ __half g_Vh[NTOK*DM];
__device__ __half g_Gh[NTOK*DM];
__device__ __half g_Xh[NTOK*DM];
__device__ __half g_Yh[NTOK*DM];
__device__ __half g_Wh4[4*DM*DM];
__device__ __half g_Woh[DM*DM];
__device__ float  g_R[NTOK*DM];

__device__ __forceinline__ uint32_t smem_u32(const void* p) {
    uint32_t a;
    asm("{ .reg .u64 t; cvta.to.shared.u64 t, %1; cvt.u32.u64 %0, t; }" : "=r"(a) : "l"(p));
    return a;
}
__device__ __forceinline__ uint32_t h2_u32(__half2 h) {
    union { __half2 h2; uint32_t u; } cvt; cvt.h2 = h; return cvt.u;
}
__device__ __forceinline__ void cpa16(uint32_t dst, const void* src) {
    asm volatile("cp.async.cg.shared.global [%0], [%1], 16;" :: "r"(dst), "l"(src) : "memory");
}
__device__ __forceinline__ void mma_f16(float* c, const uint32_t* a, const uint32_t* b) {
    asm volatile(
        "mma.sync.aligned.m16n8k16.row.col.f32.f16.f16.f32 "
        "{%0,%1,%2,%3}, {%4,%5,%6,%7}, {%8,%9}, {%0,%1,%2,%3};"
        : "+f"(c[0]), "+f"(c[1]), "+f"(c[2]), "+f"(c[3])
        : "r"(a[0]), "r"(a[1]), "r"(a[2]), "r"(a[3]), "r"(b[0]), "r"(b[1]));
}
__device__ __forceinline__ void ldsm_x4(uint32_t* r, uint32_t a) {
    asm volatile("ldmatrix.sync.aligned.m8n8.x4.shared.b16 {%0,%1,%2,%3}, [%4];"
        : "=r"(r[0]), "=r"(r[1]), "=r"(r[2]), "=r"(r[3]) : "r"(a));
}
__device__ __forceinline__ void ldsm_x4t(uint32_t* r, uint32_t a) {
    asm volatile("ldmatrix.sync.aligned.m8n8.x4.trans.shared.b16 {%0,%1,%2,%3}, [%4];"
        : "=r"(r[0]), "=r"(r[1]), "=r"(r[2]), "=r"(r[3]) : "r"(a));
}

struct GemmCfgH {
    void* out[4];
    const float* bias[4];
    int act[4];
};

// ---------------------------------------------------------------------------
// fp16 mma.sync GEMM with ldmatrix fragment loads (unchanged from round 13)
// ---------------------------------------------------------------------------
template<int HOUT>
__global__ __launch_bounds__(256) void gemm_h(
    const __half* __restrict__ A, const __half* __restrict__ Bt, GemmCfgH cfg)
{
    extern __shared__ __align__(16) __half gsm[];
    const int t = threadIdx.x;
    const int wid = t >> 5, lane = t & 31;
    const int wm = wid >> 2, wn = wid & 3;
    const int m0 = blockIdx.y * 128, n0 = blockIdx.x * 128;
    const int bsel = n0 >> 10;
    const int ncol0 = n0 & 1023;
    const int lq = lane >> 2, lr = lane & 3;

    const uint32_t sA0 = smem_u32(gsm);
    const uint32_t sB0 = sA0 + GBUF * 2;
    const uint32_t bufStride = 2 * GBUF * 2;

    const int l15 = lane & 15;
    const int k8a = (lane & 16) ? 8 : 0;
    const uint32_t aoff = ((wm * 64 + l15) * SH + k8a) * 2;
    const uint32_t boff = ((wn * 32 + (lane & 7) + k8a) * SH + ((lane & 8) ? 8 : 0)) * 2;

    float acc[4][4][4];
    #pragma unroll
    for (int i = 0; i < 4; i++)
        #pragma unroll
        for (int j = 0; j < 4; j++)
            #pragma unroll
            for (int q = 0; q < 4; q++) acc[i][j][q] = 0.f;

    auto loadTile = [&](int kt, int buf) {
        const int k0 = kt * KTH;
        #pragma unroll
        for (int i = 0; i < 2; i++) {
            int s = t + i * 256;
            int row = s >> 2, seg = s & 3;
            cpa16(sA0 + buf * bufStride + (row * SH + seg * 8) * 2,
                  A + (size_t)(m0 + row) * DM + k0 + seg * 8);
            cpa16(sB0 + buf * bufStride + (row * SH + seg * 8) * 2,
                  Bt + (size_t)(n0 + row) * DM + k0 + seg * 8);
        }
        asm volatile("cp.async.commit_group;" ::: "memory");
    };

    loadTile(0, 0);

    for (int kt = 0; kt < NKTH; kt++) {
        if (kt + 1 < NKTH) {
            loadTile(kt + 1, (kt + 1) & 1);
            asm volatile("cp.async.wait_group 1;" ::: "memory");
        } else {
            asm volatile("cp.async.wait_group 0;" ::: "memory");
        }
        __syncthreads();

        const uint32_t aB = sA0 + (kt & 1) * bufStride;
        const uint32_t bB = sB0 + (kt & 1) * bufStride;

        #pragma unroll
        for (int ks = 0; ks < 2; ks++) {
            const uint32_t kb = ks * 32;
            uint32_t af[4][4], b01[4], b23[4];
            #pragma unroll
            for (int mi = 0; mi < 4; mi++)
                ldsm_x4(af[mi], aB + aoff + mi * (16 * SH * 2) + kb);
            ldsm_x4(b01, bB + boff + kb);
            ldsm_x4(b23, bB + boff + 16 * SH * 2 + kb);
            #pragma unroll
            for (int mi = 0; mi < 4; mi++) {
                mma_f16(acc[mi][0], af[mi], b01 + 0);
                mma_f16(acc[mi][1], af[mi], b01 + 2);
                mma_f16(acc[mi][2], af[mi], b23 + 0);
                mma_f16(acc[mi][3], af[mi], b23 + 2);
            }
        }
        __syncthreads();
    }

    const float* bp = cfg.bias[bsel];
    const int act = cfg.act[bsel];

    #pragma unroll
    for (int mi = 0; mi < 4; mi++) {
        #pragma unroll
        for (int ni = 0; ni < 4; ni++) {
            const int col = ncol0 + wn * 32 + ni * 8 + lr * 2;
            float b0 = 0.f, b1 = 0.f;
            if (bp) { b0 = bp[col]; b1 = bp[col + 1]; }
            #pragma unroll
            for (int h = 0; h < 2; h++) {
                const int row = m0 + wm * 64 + mi * 16 + lq + h * 8;
                float z0 = acc[mi][ni][h * 2 + 0] + b0;
                float z1 = acc[mi][ni][h * 2 + 1] + b1;
                if (act) {
                    z0 = z0 / (1.0f + expf(-z0));
                    z1 = z1 / (1.0f + expf(-z1));
                }
                if (HOUT) {
                    *(__half2*)((__half*)cfg.out[bsel] + (size_t)row * DM + col) =
                        __floats2half2_rn(z0, z1);
                } else {
                    float2 v = make_float2(z0, z1);
                    *(float2*)((float*)cfg.out[bsel] + (size_t)row * DM + col) = v;
                }
            }
        }
    }
}

// ---------------------------------------------------------------------------
// Prep
// ---------------------------------------------------------------------------
__global__ __launch_bounds__(256) void cvt_x(const float* __restrict__ in,
                                             __half* __restrict__ out)
{
    size_t i = ((size_t)blockIdx.x * 256 + threadIdx.x) * 8;
    float4 v0 = *(const float4*)(in + i);
    float4 v1 = *(const float4*)(in + i + 4);
    uint32_t o[4];
    o[0] = h2_u32(__floats2half2_rn(v0.x, v0.y));
    o[1] = h2_u32(__floats2half2_rn(v0.z, v0.w));
    o[2] = h2_u32(__floats2half2_rn(v1.x, v1.y));
    o[3] = h2_u32(__floats2half2_rn(v1.z, v1.w));
    *(uint4*)(out + i) = make_uint4(o[0], o[1], o[2], o[3]);
}

__global__ __launch_bounds__(256) void transpose_cvt5(
    const float* Wq, const float* Wk, const float* Wv, const float* Wg,
    const float* Wo, __half* Wh4, __half* Woh)
{
    __shared__ float tile[32][33];
    const int z = blockIdx.z;
    const float* W = (z == 0) ? Wq : (z == 1) ? Wk : (z == 2) ? Wv : (z == 3) ? Wg : Wo;
    __half* Wt = (z < 4) ? (Wh4 + (size_t)z * DM * DM) : Woh;
    const int k0 = blockIdx.x * 32, n0 = blockIdx.y * 32;
    const int tx = threadIdx.x & 31, ty = threadIdx.x >> 5;
    #pragma unroll
    for (int i = 0; i < 32; i += 8)
        tile[ty + i][tx] = W[(size_t)(k0 + ty + i) * DM + n0 + tx];
    __syncthreads();
    #pragma unroll
    for (int i = 0; i < 32; i += 8)
        Wt[(size_t)(n0 + ty + i) * DM + k0 + tx] = __float2half_rn(tile[tx][ty + i]);
}

// ---------------------------------------------------------------------------
// Retention fp16: S never leaves registers. Split-k over tokens:
// warp (wm,wn) computes S[16 x 32] for its token half, packs C-frags ->
// A-frags (bit-identical layouts), accumulates partial O[16 x 64]; cross-warp
// (wn) reduction once at the end through SMEM. One __syncthreads per iter.
// ---------------------------------------------------------------------------
__global__ __launch_bounds__(256, 3) void retention_h(
    const __half* __restrict__ Q, const __half* __restrict__ K,
    const __half* __restrict__ V, float* __restrict__ R)
{
    extern __shared__ __align__(16) __half rsm[];
    const uint32_t sQ = smem_u32(rsm);
    const uint32_t sK = sQ + RBUF * 2;       // 2 buffers
    const uint32_t sV = sK + 2 * RBUF * 2;   // 2 buffers

    const int idx = blockIdx.x;
    const int qb = (TT/64 - 1) - (idx >> 5);
    const int rem = idx & 31;
    const int h = 15 - (rem >> 1);
    const int b = rem & 1;

    const int t = threadIdx.x;
    const int wid = t >> 5, lane = t & 31;
    const int wm = wid >> 1, wn = wid & 1;            // 4(m) x 2(k-split)
    const int lq = lane >> 2, lr = lane & 3;
    const size_t base = (size_t)b * TT * DM + (size_t)h * DH;
    const int t0 = qb * 64;

    const int l15 = lane & 15;
    const int k8a = (lane & 16) ? 8 : 0;
    const uint32_t qoff  = ((wm * 16 + l15) * RST + k8a) * 2;
    const uint32_t koffB = ((wn * 32 + (lane & 7) + k8a) * RST + ((lane & 8) ? 8 : 0)) * 2;
    const uint32_t voffB = (l15 * RST + k8a) * 2;

    // Q tile
    #pragma unroll
    for (int i = 0; i < 2; i++) {
        int s = t + i * 256;
        int row = s >> 3, seg = s & 7;
        cpa16(sQ + (row * RST + seg * 8) * 2,
              Q + base + (size_t)(t0 + row) * DM + seg * 8);
    }
    asm volatile("cp.async.commit_group;" ::: "memory");

    const float gamma = 1.0f - exp2f(-(float)(5 + h));
    const float l2g   = log2f(gamma);
    float diffmax = 24.0f / (-l2g);
    int nb_back = (diffmax > 1.0e8f) ? qb : ((int)(diffmax * (1.0f / 64.0f)) + 2);
    int sb0 = qb - nb_back; if (sb0 < 0) sb0 = 0;
    const int nit = qb - sb0 + 1;

    float rowf[2], colf[8];
    #pragma unroll
    for (int i = 0; i < 2; i++)
        rowf[i] = exp2f(l2g * (float)(wm * 16 + lq + 8 * i)) * 0.125f;
    #pragma unroll
    for (int ni = 0; ni < 4; ni++)
        #pragma unroll
        for (int j = 0; j < 2; j++)
            colf[ni * 2 + j] = exp2f(-l2g * (float)(wn * 32 + ni * 8 + 2 * lr + j));

    auto loadKV = [&](int sb, int buf) {
        #pragma unroll
        for (int i = 0; i < 2; i++) {
            int s = t + i * 256;
            int row = s >> 3, seg = s & 7;
            cpa16(sK + (buf * RBUF + row * RST + seg * 8) * 2,
                  K + base + (size_t)(sb * 64 + row) * DM + seg * 8);
            cpa16(sV + (buf * RBUF + row * RST + seg * 8) * 2,
                  V + base + (size_t)(sb * 64 + row) * DM + seg * 8);
        }
        asm volatile("cp.async.commit_group;" ::: "memory");
    };

    loadKV(sb0, 0);

    float oacc[8][4];
    #pragma unroll
    for (int nj = 0; nj < 8; nj++)
        #pragma unroll
        for (int q = 0; q < 4; q++) oacc[nj][q] = 0.f;

    for (int it = 0; it < nit; it++) {
        const int sb = sb0 + it;
        const int buf = it & 1;
        asm volatile("cp.async.wait_group 0;" ::: "memory");
        __syncthreads();

        // ---- S = Q K^T (warp's 32-token slice) ----
        float sacc[4][4];
        #pragma unroll
        for (int ni = 0; ni < 4; ni++)
            #pragma unroll
            for (int q = 0; q < 4; q++) sacc[ni][q] = 0.f;

        const uint32_t kB = sK + buf * RBUF * 2;
        #pragma unroll
        for (int ks = 0; ks < 4; ks++) {
            const uint32_t kb = ks * 32;
            uint32_t af[4], b01[4], b23[4];
            ldsm_x4(af, sQ + qoff + kb);
            ldsm_x4(b01, kB + koffB + kb);
            ldsm_x4(b23, kB + koffB + 16 * RST * 2 + kb);
            mma_f16(sacc[0], af, b01 + 0);
            mma_f16(sacc[1], af, b01 + 2);
            mma_f16(sacc[2], af, b23 + 0);
            mma_f16(sacc[3], af, b23 + 2);
        }

        if (it + 1 < nit) loadKV(sb + 1, (it + 1) & 1);
        else asm volatile("cp.async.commit_group;" ::: "memory");

        // ---- decay + causal in regs; pack C-frags as A-frags ----
        const float pb = exp2f(l2g * (float)(64 * (qb - sb)));
        const bool diag = (sb == qb);
        uint32_t afr[2][4];
        #pragma unroll
        for (int ni = 0; ni < 4; ni++) {
            const int nl0 = wn * 32 + ni * 8 + 2 * lr;
            const float wr0 = rowf[0] * pb;
            const float wr1 = rowf[1] * pb;
            const int m0r = wm * 16 + lq;
            float v0 = sacc[ni][0] * (wr0 * colf[ni * 2 + 0]);
            float v1 = sacc[ni][1] * (wr0 * colf[ni * 2 + 1]);
            float v2 = sacc[ni][2] * (wr1 * colf[ni * 2 + 0]);
            float v3 = sacc[ni][3] * (wr1 * colf[ni * 2 + 1]);
            if (diag && nl0     > m0r)     v0 = 0.f;
            if (diag && nl0 + 1 > m0r)     v1 = 0.f;
            if (diag && nl0     > m0r + 8) v2 = 0.f;
            if (diag && nl0 + 1 > m0r + 8) v3 = 0.f;
            afr[ni >> 1][(ni & 1) * 2 + 0] = h2_u32(__floats2half2_rn(v0, v1));
            afr[ni >> 1][(ni & 1) * 2 + 1] = h2_u32(__floats2half2_rn(v2, v3));
        }

        // ---- O partial += S V (B via ldmatrix.trans from natural V) ----
        const uint32_t vB = sV + buf * RBUF * 2;
        #pragma unroll
        for (int kb = 0; kb < 2; kb++) {
            const uint32_t rowb = (uint32_t)((wn * 32 + kb * 16) * RST) * 2;
            #pragma unroll
            for (int nj4 = 0; nj4 < 4; nj4++) {
                uint32_t bq[4];
                ldsm_x4t(bq, vB + voffB + rowb + nj4 * 32);   // 16 halfs = 32 B
                mma_f16(oacc[nj4 * 2 + 0], afr[kb], bq + 0);
                mma_f16(oacc[nj4 * 2 + 1], afr[kb], bq + 2);
            }
        }
    }

    // ---- cross-warp (wn) reduction of O partials, then write R ----
    __syncthreads();                       // all iters done; smem reusable
    float* red = (float*)rsm;              // [64][66] f32 = 16.9 KB
    const int RRST = 66;
    if (wn == 1) {
        #pragma unroll
        for (int nj = 0; nj < 8; nj++)
            #pragma unroll
            for (int h_ = 0; h_ < 2; h_++) {
                const int r = wm * 16 + lq + 8 * h_;
                float2 v = make_float2(oacc[nj][h_ * 2 + 0], oacc[nj][h_ * 2 + 1]);
                *(float2*)&red[r * RRST + nj * 8 + 2 * lr] = v;
            }
    }
    __syncthreads();
    if (wn == 0) {
        #pragma unroll
        for (int nj = 0; nj < 8; nj++)
            #pragma unroll
            for (int h_ = 0; h_ < 2; h_++) {
                const int r = wm * 16 + lq + 8 * h_;
                const int col = nj * 8 + 2 * lr;
                float2 p = *(float2*)&red[r * RRST + col];
                float2 v = make_float2(oacc[nj][h_ * 2 + 0] + p.x,
                                       oacc[nj][h_ * 2 + 1] + p.y);
                *(float2*)(R + base + (size_t)(t0 + r) * DM + col) = v;
            }
    }
}

// ---------------------------------------------------------------------------
// LayerNorm * gate: R f32, G half -> Y half
// ---------------------------------------------------------------------------
__global__ __launch_bounds__(256) void ln_gate_h(
    const float* __restrict__ R, const __half* __restrict__ G,
    const float* __restrict__ lng, const float* __restrict__ lnb,
    __half* __restrict__ Y)
{
    __shared__ float red[8];
    const int row = blockIdx.x;
    const int t = threadIdx.x;
    const size_t off = (size_t)row * DM + t * 4;

    float4 x = *(const float4*)(R + off);

    float s = x.x + x.y + x.z + x.w;
    #pragma unroll
    for (int o = 16; o > 0; o >>= 1) s += __shfl_xor_sync(0xffffffffu, s, o);
    if ((t & 31) == 0) red[t >> 5] = s;
    __syncthreads();
    float tot = red[0] + red[1] + red[2] + red[3] + red[4] + red[5] + red[6] + red[7];
    const float mu = tot * (1.0f / 1024.0f);

    float d0 = x.x - mu, d1 = x.y - mu, d2 = x.z - mu, d3 = x.w - mu;
    float sq = d0 * d0 + d1 * d1 + d2 * d2 + d3 * d3;
    #pragma unroll
    for (int o = 16; o > 0; o >>= 1) sq += __shfl_xor_sync(0xffffffffu, sq, o);
    __syncthreads();
    if ((t & 31) == 0) red[t >> 5] = sq;
    __syncthreads();
    float totsq = red[0] + red[1] + red[2] + red[3] + red[4] + red[5] + red[6] + red[7];
    const float rstd = rsqrtf(totsq * (1.0f / 1024.0f) + 1e-3f);

    float4 g4 = *(const float4*)(lng + t * 4);
    float4 b4 = *(const float4*)(lnb + t * 4);
    uint2 gu = *(const uint2*)(G + off);
    float2 ga = __half22float2(*(__half2*)&gu.x);
    float2 gb = __half22float2(*(__half2*)&gu.y);

    __half2 y0 = __floats2half2_rn((d0 * rstd * g4.x + b4.x) * ga.x,
                                   (d1 * rstd * g4.y + b4.y) * ga.y);
    __half2 y1 = __floats2half2_rn((d2 * rstd * g4.z + b4.z) * gb.x,
                                   (d3 * rstd * g4.w + b4.w) * gb.y);
    __half2* yp = (__half2*)(Y + off);
    yp[0] = y0;
    yp[1] = y1;
}

// ---------------------------------------------------------------------------
extern "C" void kernel_launch(void* const* d_in, const int* in_sizes, int n_in,
                              void* d_out, int out_size)
{
    const float* x   = (const float*)d_in[0];
    const float* Wq  = (const float*)d_in[1];
    const float* Wk  = (const float*)d_in[2];
    const float* Wv  = (const float*)d_in[3];
    const float* Wg  = (const float*)d_in[4];
    const float* bg  = (const float*)d_in[5];
    const float* Wo  = (const float*)d_in[6];
    const float* bo  = (const float*)d_in[7];
    const float* lng = (const float*)d_in[8];
    const float* lnb = (const float*)d_in[9];

    __half *Qh, *Kh, *Vh, *Gh, *Xh, *Yh, *Wh4, *Woh;
    float *R;
    cudaGetSymbolAddress((void**)&Qh,  g_Qh);
    cudaGetSymbolAddress((void**)&Kh,  g_Kh);
    cudaGetSymbolAddress((void**)&Vh,  g_Vh);
    cudaGetSymbolAddress((void**)&Gh,  g_Gh);
    cudaGetSymbolAddress((void**)&Xh,  g_Xh);
    cudaGetSymbolAddress((void**)&Yh,  g_Yh);
    cudaGetSymbolAddress((void**)&Wh4, g_Wh4);
    cudaGetSymbolAddress((void**)&Woh, g_Woh);
    cudaGetSymbolAddress((void**)&R,   g_R);

    cvt_x<<<(NTOK * DM) / (256 * 8), 256>>>(x, Xh);
    transpose_cvt5<<<dim3(32, 32, 5), 256>>>(Wq, Wk, Wv, Wg, Wo, Wh4, Woh);

    GemmCfgH c1;
    c1.out[0] = Qh; c1.out[1] = Kh; c1.out[2] = Vh; c1.out[3] = Gh;
    c1.bias[0] = nullptr; c1.bias[1] = nullptr; c1.bias[2] = nullptr; c1.bias[3] = bg;
    c1.act[0] = 0; c1.act[1] = 0; c1.act[2] = 0; c1.act[3] = 1;
    gemm_h<1><<<dim3(32, 32), 256, GEMM_SMEM>>>(Xh, Wh4, c1);

    cudaFuncSetAttribute(retention_h, cudaFuncAttributeMaxDynamicSharedMemorySize, RET_SMEM);
    retention_h<<<dim3((TT/64) * NH * BB), 256, RET_SMEM>>>(Qh, Kh, Vh, R);

    ln_gate_h<<<NTOK, 256>>>(R, Gh, lng, lnb, Yh);

    GemmCfgH c2;
    c2.out[0] = d_out; c2.out[1] = nullptr; c2.out[2] = nullptr; c2.out[3] = nullptr;
    c2.bias[0] = bo; c2.bias[1] = nullptr; c2.bias[2] = nullptr; c2.bias[3] = nullptr;
    c2.act[0] = 0; c2.act[1] = 0; c2.act[2] = 0; c2.act[3] = 0;
    gemm_h<0><<<dim3(8, 32), 256, GEMM_SMEM>>>(Yh, Woh, c2);
}

// round 15
// speedup vs baseline: 7.1871x; 1.0834x over previous
#include <cuda_runtime.h>
#include <cuda_fp16.h>
#include <math.h>
#include <stdint.h>

#define NTOK 4096   // B*T
#define DM   1024
#define NH   16
#define DH   64
#define TT   2048
#define BB   2

// ---- fp16 gemm config (A via smem/ldmatrix; B via packed-fragment LDG) ----
#define KTH   32            // k-tile (halfs)
#define NKTH  (DM/KTH)      // 32
#define NKK   (DM/16)       // 64 k16 steps
#define SH    40            // padded k-stride (halfs)
#define GBUF  (128*SH)      // halfs per A stage
#define GEMM_SMEM (2*GBUF*2)     // 20480 B (A only, 2 stages)

// ---- retention smem: stride 72 halfs ----
#define RST   72
#define RBUF  (64*RST)
#define RET_SMEM (5*RBUF*2) // 46080 B

// Scratch (__device__ globals: allocation-free rule)
__device__ __half g_Qh[NTOK*DM];
__device__ __half g_Kh[NTOK*DM];
__device__ __half g_Vh[NTOK*DM];
__device__ __half g_Gh[NTOK*DM];
__device__ __half g_Xh[NTOK*DM];
__device__ __half g_Yh[NTOK*DM];
__device__ uint2  g_Bp4[512*64*32];   // QKVG weights, fragment-packed (8 MB)
__device__ uint2  g_BpO[128*64*32];   // Wo, fragment-packed (2 MB)
__device__ float  g_R[NTOK*DM];

__device__ __forceinline__ uint32_t smem_u32(const void* p) {
    uint32_t a;
    asm("{ .reg .u64 t; cvta.to.shared.u64 t, %1; cvt.u32.u64 %0, t; }" : "=r"(a) : "l"(p));
    return a;
}
__device__ __forceinline__ uint32_t h2_u32(__half2 h) {
    union { __half2 h2; uint32_t u; } cvt; cvt.h2 = h; return cvt.u;
}
__device__ __forceinline__ void cpa16(uint32_t dst, const void* src) {
    asm volatile("cp.async.cg.shared.global [%0], [%1], 16;" :: "r"(dst), "l"(src) : "memory");
}
__device__ __forceinline__ void mma_f16(float* c, const uint32_t* a, const uint32_t* b) {
    asm volatile(
        "mma.sync.aligned.m16n8k16.row.col.f32.f16.f16.f32 "
        "{%0,%1,%2,%3}, {%4,%5,%6,%7}, {%8,%9}, {%0,%1,%2,%3};"
        : "+f"(c[0]), "+f"(c[1]), "+f"(c[2]), "+f"(c[3])
        : "r"(a[0]), "r"(a[1]), "r"(a[2]), "r"(a[3]), "r"(b[0]), "r"(b[1]));
}
__device__ __forceinline__ void ldsm_x4(uint32_t* r, uint32_t a) {
    asm volatile("ldmatrix.sync.aligned.m8n8.x4.shared.b16 {%0,%1,%2,%3}, [%4];"
        : "=r"(r[0]), "=r"(r[1]), "=r"(r[2]), "=r"(r[3]) : "r"(a));
}
__device__ __forceinline__ void ldsm_x4t(uint32_t* r, uint32_t a) {
    asm volatile("ldmatrix.sync.aligned.m8n8.x4.trans.shared.b16 {%0,%1,%2,%3}, [%4];"
        : "=r"(r[0]), "=r"(r[1]), "=r"(r[2]), "=r"(r[3]) : "r"(a));
}

struct GemmCfgH {
    void* out[4];
    const float* bias[4];
    int act[4];
};

// ---------------------------------------------------------------------------
// fp16 GEMM: A via cp.async+ldmatrix; B fragments via LDG.64 from packed
// weights (register double-buffered, one k16 lookahead). 8 warps (2x4).
// ---------------------------------------------------------------------------
template<int HOUT>
__global__ __launch_bounds__(256) void gemm_h(
    const __half* __restrict__ A, const uint2* __restrict__ Bp, GemmCfgH cfg)
{
    extern __shared__ __align__(16) __half gsm[];
    const int t = threadIdx.x;
    const int wid = t >> 5, lane = t & 31;
    const int wm = wid >> 2, wn = wid & 3;
    const int m0 = blockIdx.y * 128, n0 = blockIdx.x * 128;
    const int bsel = n0 >> 10;
    const int ncol0 = n0 & 1023;
    const int lq = lane >> 2, lr = lane & 3;

    const uint32_t sA0 = smem_u32(gsm);
    const uint32_t bufStride = GBUF * 2;  // bytes per A stage

    const int l15 = lane & 15;
    const int k8a = (lane & 16) ? 8 : 0;
    const uint32_t aoff = ((wm * 64 + l15) * SH + k8a) * 2;

    // packed-B base for this warp's 4 n8 blocks
    const int n8base = (n0 + wn * 32) >> 3;
    const uint2* bb = Bp + (size_t)n8base * (64 * 32) + lane;

    float acc[4][4][4];
    #pragma unroll
    for (int i = 0; i < 4; i++)
        #pragma unroll
        for (int j = 0; j < 4; j++)
            #pragma unroll
            for (int q = 0; q < 4; q++) acc[i][j][q] = 0.f;

    auto loadTile = [&](int kt, int buf) {
        const int k0 = kt * KTH;
        #pragma unroll
        for (int i = 0; i < 2; i++) {
            int s = t + i * 256;
            int row = s >> 2, seg = s & 3;
            cpa16(sA0 + buf * bufStride + (row * SH + seg * 8) * 2,
                  A + (size_t)(m0 + row) * DM + k0 + seg * 8);
        }
        asm volatile("cp.async.commit_group;" ::: "memory");
    };

    // B fragment register double-buffer
    uint2 breg[2][4];
    #pragma unroll
    for (int j = 0; j < 4; j++) breg[0][j] = bb[(size_t)j * (64 * 32)];

    loadTile(0, 0);

    for (int kt = 0; kt < NKTH; kt++) {
        if (kt + 1 < NKTH) {
            loadTile(kt + 1, (kt + 1) & 1);
            asm volatile("cp.async.wait_group 1;" ::: "memory");
        } else {
            asm volatile("cp.async.wait_group 0;" ::: "memory");
        }
        __syncthreads();

        const uint32_t aB = sA0 + (kt & 1) * bufStride;

        #pragma unroll
        for (int ks = 0; ks < 2; ks++) {
            const int kk = kt * 2 + ks;
            // prefetch B fragments for kk+1
            if (kk + 1 < NKK) {
                #pragma unroll
                for (int j = 0; j < 4; j++)
                    breg[(kk + 1) & 1][j] = bb[(size_t)j * (64 * 32) + (kk + 1) * 32];
            }
            uint32_t af[4][4];
            #pragma unroll
            for (int mi = 0; mi < 4; mi++)
                ldsm_x4(af[mi], aB + aoff + mi * (16 * SH * 2) + ks * 32);
            const uint2* bc = breg[kk & 1];
            #pragma unroll
            for (int mi = 0; mi < 4; mi++) {
                #pragma unroll
                for (int ni = 0; ni < 4; ni++) {
                    uint32_t bf[2] = { bc[ni].x, bc[ni].y };
                    mma_f16(acc[mi][ni], af[mi], bf);
                }
            }
        }
        __syncthreads();
    }

    const float* bp = cfg.bias[bsel];
    const int act = cfg.act[bsel];

    #pragma unroll
    for (int mi = 0; mi < 4; mi++) {
        #pragma unroll
        for (int ni = 0; ni < 4; ni++) {
            const int col = ncol0 + wn * 32 + ni * 8 + lr * 2;
            float b0 = 0.f, b1 = 0.f;
            if (bp) { b0 = bp[col]; b1 = bp[col + 1]; }
            #pragma unroll
            for (int h = 0; h < 2; h++) {
                const int row = m0 + wm * 64 + mi * 16 + lq + h * 8;
                float z0 = acc[mi][ni][h * 2 + 0] + b0;
                float z1 = acc[mi][ni][h * 2 + 1] + b1;
                if (act) {
                    z0 = z0 / (1.0f + expf(-z0));
                    z1 = z1 / (1.0f + expf(-z1));
                }
                if (HOUT) {
                    *(__half2*)((__half*)cfg.out[bsel] + (size_t)row * DM + col) =
                        __floats2half2_rn(z0, z1);
                } else {
                    float2 v = make_float2(z0, z1);
                    *(float2*)((float*)cfg.out[bsel] + (size_t)row * DM + col) = v;
                }
            }
        }
    }
}

// ---------------------------------------------------------------------------
// Prep: X f32 -> half; 5 weights -> fragment-packed half (one launch)
// ---------------------------------------------------------------------------
__global__ __launch_bounds__(256) void cvt_x(const float* __restrict__ in,
                                             __half* __restrict__ out)
{
    size_t i = ((size_t)blockIdx.x * 256 + threadIdx.x) * 8;
    float4 v0 = *(const float4*)(in + i);
    float4 v1 = *(const float4*)(in + i + 4);
    uint32_t o[4];
    o[0] = h2_u32(__floats2half2_rn(v0.x, v0.y));
    o[1] = h2_u32(__floats2half2_rn(v0.z, v0.w));
    o[2] = h2_u32(__floats2half2_rn(v1.x, v1.y));
    o[3] = h2_u32(__floats2half2_rn(v1.z, v1.w));
    *(uint4*)(out + i) = make_uint4(o[0], o[1], o[2], o[3]);
}

// Pack W[k][n] f32 -> mma B-fragment order: [n8][k16][lane]{b0,b1}
__global__ __launch_bounds__(256) void transpose_pack5(
    const float* Wq, const float* Wk, const float* Wv, const float* Wg,
    const float* Wo, uint2* Bp4, uint2* BpO)
{
    __shared__ float tile[32][33];
    const int z = blockIdx.z;
    const float* W = (z == 0) ? Wq : (z == 1) ? Wk : (z == 2) ? Wv : (z == 3) ? Wg : Wo;
    const int k0 = blockIdx.x * 32, n0 = blockIdx.y * 32;
    const int tx = threadIdx.x & 31, ty = threadIdx.x >> 5;
    #pragma unroll
    for (int i = 0; i < 32; i += 8)
        tile[ty + i][tx] = W[(size_t)(k0 + ty + i) * DM + n0 + tx];
    __syncthreads();

    const int w = threadIdx.x >> 5, l = threadIdx.x & 31;
    const int kkl = w >> 2, jl = w & 3;            // k16 block, n8 block in tile
    const int nl = jl * 8 + (l >> 2);
    const int kl = kkl * 16 + 2 * (l & 3);
    uint32_t b0 = h2_u32(__floats2half2_rn(tile[kl][nl],     tile[kl + 1][nl]));
    uint32_t b1 = h2_u32(__floats2half2_rn(tile[kl + 8][nl], tile[kl + 9][nl]));
    const int kkg = (k0 >> 4) + kkl;
    if (z < 4) {
        size_t jg = (size_t)z * 128 + (n0 >> 3) + jl;
        Bp4[(jg * 64 + kkg) * 32 + l] = make_uint2(b0, b1);
    } else {
        size_t jg = (size_t)(n0 >> 3) + jl;
        BpO[(jg * 64 + kkg) * 32 + l] = make_uint2(b0, b1);
    }
}

// ---------------------------------------------------------------------------
// Retention fp16: S in registers (C-frag == A-frag), split-k over tokens,
// cross-warp reduction at the end. Diagonal fully-masked warp tiles skipped.
// ---------------------------------------------------------------------------
__global__ __launch_bounds__(256, 3) void retention_h(
    const __half* __restrict__ Q, const __half* __restrict__ K,
    const __half* __restrict__ V, float* __restrict__ R)
{
    extern __shared__ __align__(16) __half rsm[];
    const uint32_t sQ = smem_u32(rsm);
    const uint32_t sK = sQ + RBUF * 2;
    const uint32_t sV = sK + 2 * RBUF * 2;

    const int idx = blockIdx.x;
    const int qb = (TT/64 - 1) - (idx >> 5);
    const int rem = idx & 31;
    const int h = 15 - (rem >> 1);
    const int b = rem & 1;

    const int t = threadIdx.x;
    const int wid = t >> 5, lane = t & 31;
    const int wm = wid >> 1, wn = wid & 1;
    const int lq = lane >> 2, lr = lane & 3;
    const size_t base = (size_t)b * TT * DM + (size_t)h * DH;
    const int t0 = qb * 64;

    const int l15 = lane & 15;
    const int k8a = (lane & 16) ? 8 : 0;
    const uint32_t qoff  = ((wm * 16 + l15) * RST + k8a) * 2;
    const uint32_t koffB = ((wn * 32 + (lane & 7) + k8a) * RST + ((lane & 8) ? 8 : 0)) * 2;
    const uint32_t voffB = (l15 * RST + k8a) * 2;

    #pragma unroll
    for (int i = 0; i < 2; i++) {
        int s = t + i * 256;
        int row = s >> 3, seg = s & 7;
        cpa16(sQ + (row * RST + seg * 8) * 2,
              Q + base + (size_t)(t0 + row) * DM + seg * 8);
    }
    asm volatile("cp.async.commit_group;" ::: "memory");

    const float gamma = 1.0f - exp2f(-(float)(5 + h));
    const float l2g   = log2f(gamma);
    float diffmax = 24.0f / (-l2g);
    int nb_back = (diffmax > 1.0e8f) ? qb : ((int)(diffmax * (1.0f / 64.0f)) + 2);
    int sb0 = qb - nb_back; if (sb0 < 0) sb0 = 0;
    const int nit = qb - sb0 + 1;

    float rowf[2], colf[8];
    #pragma unroll
    for (int i = 0; i < 2; i++)
        rowf[i] = exp2f(l2g * (float)(wm * 16 + lq + 8 * i)) * 0.125f;
    #pragma unroll
    for (int ni = 0; ni < 4; ni++)
        #pragma unroll
        for (int j = 0; j < 2; j++)
            colf[ni * 2 + j] = exp2f(-l2g * (float)(wn * 32 + ni * 8 + 2 * lr + j));

    auto loadKV = [&](int sb, int buf) {
        #pragma unroll
        for (int i = 0; i < 2; i++) {
            int s = t + i * 256;
            int row = s >> 3, seg = s & 7;
            cpa16(sK + (buf * RBUF + row * RST + seg * 8) * 2,
                  K + base + (size_t)(sb * 64 + row) * DM + seg * 8);
            cpa16(sV + (buf * RBUF + row * RST + seg * 8) * 2,
                  V + base + (size_t)(sb * 64 + row) * DM + seg * 8);
        }
        asm volatile("cp.async.commit_group;" ::: "memory");
    };

    loadKV(sb0, 0);

    float oacc[8][4];
    #pragma unroll
    for (int nj = 0; nj < 8; nj++)
        #pragma unroll
        for (int q = 0; q < 4; q++) oacc[nj][q] = 0.f;

    for (int it = 0; it < nit; it++) {
        const int sb = sb0 + it;
        const int buf = it & 1;
        asm volatile("cp.async.wait_group 0;" ::: "memory");
        __syncthreads();

        const bool diag = (sb == qb);
        const bool skipw = diag && (wn == 1) && (wm < 2);  // fully-masked tile

        float sacc[4][4];
        uint32_t afr[2][4];

        if (!skipw) {
            #pragma unroll
            for (int ni = 0; ni < 4; ni++)
                #pragma unroll
                for (int q = 0; q < 4; q++) sacc[ni][q] = 0.f;

            const uint32_t kB = sK + buf * RBUF * 2;
            #pragma unroll
            for (int ks = 0; ks < 4; ks++) {
                const uint32_t kb = ks * 32;
                uint32_t af[4], b01[4], b23[4];
                ldsm_x4(af, sQ + qoff + kb);
                ldsm_x4(b01, kB + koffB + kb);
                ldsm_x4(b23, kB + koffB + 16 * RST * 2 + kb);
                mma_f16(sacc[0], af, b01 + 0);
                mma_f16(sacc[1], af, b01 + 2);
                mma_f16(sacc[2], af, b23 + 0);
                mma_f16(sacc[3], af, b23 + 2);
            }
        }

        if (it + 1 < nit) loadKV(sb + 1, (it + 1) & 1);
        else asm volatile("cp.async.commit_group;" ::: "memory");

        if (!skipw) {
            const float pb = exp2f(l2g * (float)(64 * (qb - sb)));
            #pragma unroll
            for (int ni = 0; ni < 4; ni++) {
                const int nl0 = wn * 32 + ni * 8 + 2 * lr;
                const float wr0 = rowf[0] * pb;
                const float wr1 = rowf[1] * pb;
                const int m0r = wm * 16 + lq;
                float v0 = sacc[ni][0] * (wr0 * colf[ni * 2 + 0]);
                float v1 = sacc[ni][1] * (wr0 * colf[ni * 2 + 1]);
                float v2 = sacc[ni][2] * (wr1 * colf[ni * 2 + 0]);
                float v3 = sacc[ni][3] * (wr1 * colf[ni * 2 + 1]);
                if (diag && nl0     > m0r)     v0 = 0.f;
                if (diag && nl0 + 1 > m0r)     v1 = 0.f;
                if (diag && nl0     > m0r + 8) v2 = 0.f;
                if (diag && nl0 + 1 > m0r + 8) v3 = 0.f;
                afr[ni >> 1][(ni & 1) * 2 + 0] = h2_u32(__floats2half2_rn(v0, v1));
                afr[ni >> 1][(ni & 1) * 2 + 1] = h2_u32(__floats2half2_rn(v2, v3));
            }

            const uint32_t vB = sV + buf * RBUF * 2;
            #pragma unroll
            for (int kb = 0; kb < 2; kb++) {
                const uint32_t rowb = (uint32_t)((wn * 32 + kb * 16) * RST) * 2;
                #pragma unroll
                for (int nj4 = 0; nj4 < 4; nj4++) {
                    uint32_t bq[4];
                    ldsm_x4t(bq, vB + voffB + rowb + nj4 * 32);
                    mma_f16(oacc[nj4 * 2 + 0], afr[kb], bq + 0);
                    mma_f16(oacc[nj4 * 2 + 1], afr[kb], bq + 2);
                }
            }
        }
    }

    // cross-warp (wn) reduction, then write R
    __syncthreads();
    float* red = (float*)rsm;
    const int RRST = 66;
    if (wn == 1) {
        #pragma unroll
        for (int nj = 0; nj < 8; nj++)
            #pragma unroll
            for (int h_ = 0; h_ < 2; h_++) {
                const int r = wm * 16 + lq + 8 * h_;
                float2 v = make_float2(oacc[nj][h_ * 2 + 0], oacc[nj][h_ * 2 + 1]);
                *(float2*)&red[r * RRST + nj * 8 + 2 * lr] = v;
            }
    }
    __syncthreads();
    if (wn == 0) {
        #pragma unroll
        for (int nj = 0; nj < 8; nj++)
            #pragma unroll
            for (int h_ = 0; h_ < 2; h_++) {
                const int r = wm * 16 + lq + 8 * h_;
                const int col = nj * 8 + 2 * lr;
                float2 p = *(float2*)&red[r * RRST + col];
                float2 v = make_float2(oacc[nj][h_ * 2 + 0] + p.x,
                                       oacc[nj][h_ * 2 + 1] + p.y);
                *(float2*)(R + base + (size_t)(t0 + r) * DM + col) = v;
            }
    }
}

// ---------------------------------------------------------------------------
// LayerNorm * gate: R f32, G half -> Y half
// ---------------------------------------------------------------------------
__global__ __launch_bounds__(256) void ln_gate_h(
    const float* __restrict__ R, const __half* __restrict__ G,
    const float* __restrict__ lng, const float* __restrict__ lnb,
    __half* __restrict__ Y)
{
    __shared__ float red[8];
    const int row = blockIdx.x;
    const int t = threadIdx.x;
    const size_t off = (size_t)row * DM + t * 4;

    float4 x = *(const float4*)(R + off);

    float s = x.x + x.y + x.z + x.w;
    #pragma unroll
    for (int o = 16; o > 0; o >>= 1) s += __shfl_xor_sync(0xffffffffu, s, o);
    if ((t & 31) == 0) red[t >> 5] = s;
    __syncthreads();
    float tot = red[0] + red[1] + red[2] + red[3] + red[4] + red[5] + red[6] + red[7];
    const float mu = tot * (1.0f / 1024.0f);

    float d0 = x.x - mu, d1 = x.y - mu, d2 = x.z - mu, d3 = x.w - mu;
    float sq = d0 * d0 + d1 * d1 + d2 * d2 + d3 * d3;
    #pragma unroll
    for (int o = 16; o > 0; o >>= 1) sq += __shfl_xor_sync(0xffffffffu, sq, o);
    __syncthreads();
    if ((t & 31) == 0) red[t >> 5] = sq;
    __syncthreads();
    float totsq = red[0] + red[1] + red[2] + red[3] + red[4] + red[5] + red[6] + red[7];
    const float rstd = rsqrtf(totsq * (1.0f / 1024.0f) + 1e-3f);

    float4 g4 = *(const float4*)(lng + t * 4);
    float4 b4 = *(const float4*)(lnb + t * 4);
    uint2 gu = *(const uint2*)(G + off);
    float2 ga = __half22float2(*(__half2*)&gu.x);
    float2 gb = __half22float2(*(__half2*)&gu.y);

    __half2 y0 = __floats2half2_rn((d0 * rstd * g4.x + b4.x) * ga.x,
                                   (d1 * rstd * g4.y + b4.y) * ga.y);
    __half2 y1 = __floats2half2_rn((d2 * rstd * g4.z + b4.z) * gb.x,
                                   (d3 * rstd * g4.w + b4.w) * gb.y);
    __half2* yp = (__half2*)(Y + off);
    yp[0] = y0;
    yp[1] = y1;
}

// ---------------------------------------------------------------------------
extern "C" void kernel_launch(void* const* d_in, const int* in_sizes, int n_in,
                              void* d_out, int out_size)
{
    const float* x   = (const float*)d_in[0];
    const float* Wq  = (const float*)d_in[1];
    const float* Wk  = (const float*)d_in[2];
    const float* Wv  = (const float*)d_in[3];
    const float* Wg  = (const float*)d_in[4];
    const float* bg  = (const float*)d_in[5];
    const float* Wo  = (const float*)d_in[6];
    const float* bo  = (const float*)d_in[7];
    const float* lng = (const float*)d_in[8];
    const float* lnb = (const float*)d_in[9];

    __half *Qh, *Kh, *Vh, *Gh, *Xh, *Yh;
    uint2 *Bp4, *BpO;
    float *R;
    cudaGetSymbolAddress((void**)&Qh,  g_Qh);
    cudaGetSymbolAddress((void**)&Kh,  g_Kh);
    cudaGetSymbolAddress((void**)&Vh,  g_Vh);
    cudaGetSymbolAddress((void**)&Gh,  g_Gh);
    cudaGetSymbolAddress((void**)&Xh,  g_Xh);
    cudaGetSymbolAddress((void**)&Yh,  g_Yh);
    cudaGetSymbolAddress((void**)&Bp4, g_Bp4);
    cudaGetSymbolAddress((void**)&BpO, g_BpO);
    cudaGetSymbolAddress((void**)&R,   g_R);

    cvt_x<<<(NTOK * DM) / (256 * 8), 256>>>(x, Xh);
    transpose_pack5<<<dim3(32, 32, 5), 256>>>(Wq, Wk, Wv, Wg, Wo, Bp4, BpO);

    GemmCfgH c1;
    c1.out[0] = Qh; c1.out[1] = Kh; c1.out[2] = Vh; c1.out[3] = Gh;
    c1.bias[0] = nullptr; c1.bias[1] = nullptr; c1.bias[2] = nullptr; c1.bias[3] = bg;
    c1.act[0] = 0; c1.act[1] = 0; c1.act[2] = 0; c1.act[3] = 1;
    gemm_h<1><<<dim3(32, 32), 256, GEMM_SMEM>>>(Xh, Bp4, c1);

    cudaFuncSetAttribute(retention_h, cudaFuncAttributeMaxDynamicSharedMemorySize, RET_SMEM);
    retention_h<<<dim3((TT/64) * NH * BB), 256, RET_SMEM>>>(Qh, Kh, Vh, R);

    ln_gate_h<<<NTOK, 256>>>(R, Gh, lng, lnb, Yh);

    GemmCfgH c2;
    c2.out[0] = d_out; c2.out[1] = nullptr; c2.out[2] = nullptr; c2.out[3] = nullptr;
    c2.bias[0] = bo; c2.bias[1] = nullptr; c2.bias[2] = nullptr; c2.bias[3] = nullptr;
    c2.act[0] = 0; c2.act[1] = 0; c2.act[2] = 0; c2.act[3] = 0;
    gemm_h<0><<<dim3(8, 32), 256, GEMM_SMEM>>>(Yh, BpO, c2);
}

// round 17
// speedup vs baseline: 7.4018x; 1.0299x over previous
#include <cuda_runtime.h>
#include <cuda_fp16.h>
#include <math.h>
#include <stdint.h>

#define NTOK 4096   // B*T
#define DM   1024
#define NH   16
#define DH   64
#define TT   2048
#define BB   2

// ---- fp16 gemm config (A via smem/ldmatrix; B via packed-fragment LDG) ----
#define KTH   64            // k-tile (halfs) — barriers halved vs 32
#define NKTH  (DM/KTH)      // 16
#define NKK   (DM/16)       // 64 k16 steps
#define SH    72            // padded k-stride (halfs); 36 words/row bank-perm
#define GBUF  (128*SH)      // halfs per A stage
#define GEMM_SMEM (2*GBUF*2)     // 36864 B (A only, 2 stages)

// ---- retention smem: stride 72 halfs ----
#define RST   72
#define RBUF  (64*RST)
#define RET_SMEM (5*RBUF*2) // 46080 B

// Scratch (__device__ globals: allocation-free rule)
__device__ __half g_Qh[NTOK*DM];
__device__ __half g_Kh[NTOK*DM];
__device__ __half g_Vh[NTOK*DM];
__device__ __half g_Gh[NTOK*DM];
__device__ __half g_Xh[NTOK*DM];
__device__ __half g_Yh[NTOK*DM];
__device__ uint2  g_Bp4[512*64*32];   // QKVG weights, fragment-packed (8 MB)
__device__ uint2  g_BpO[128*64*32];   // Wo, fragment-packed (2 MB)
__device__ float  g_R[NTOK*DM];

__device__ __forceinline__ uint32_t smem_u32(const void* p) {
    uint32_t a;
    asm("{ .reg .u64 t; cvta.to.shared.u64 t, %1; cvt.u32.u64 %0, t; }" : "=r"(a) : "l"(p));
    return a;
}
__device__ __forceinline__ uint32_t h2_u32(__half2 h) {
    union { __half2 h2; uint32_t u; } cvt; cvt.h2 = h; return cvt.u;
}
__device__ __forceinline__ void cpa16(uint32_t dst, const void* src) {
    asm volatile("cp.async.cg.shared.global [%0], [%1], 16;" :: "r"(dst), "l"(src) : "memory");
}
__device__ __forceinline__ void mma_f16(float* c, const uint32_t* a, const uint32_t* b) {
    asm volatile(
        "mma.sync.aligned.m16n8k16.row.col.f32.f16.f16.f32 "
        "{%0,%1,%2,%3}, {%4,%5,%6,%7}, {%8,%9}, {%0,%1,%2,%3};"
        : "+f"(c[0]), "+f"(c[1]), "+f"(c[2]), "+f"(c[3])
        : "r"(a[0]), "r"(a[1]), "r"(a[2]), "r"(a[3]), "r"(b[0]), "r"(b[1]));
}
__device__ __forceinline__ void ldsm_x4(uint32_t* r, uint32_t a) {
    asm volatile("ldmatrix.sync.aligned.m8n8.x4.shared.b16 {%0,%1,%2,%3}, [%4];"
        : "=r"(r[0]), "=r"(r[1]), "=r"(r[2]), "=r"(r[3]) : "r"(a));
}
__device__ __forceinline__ void ldsm_x4t(uint32_t* r, uint32_t a) {
    asm volatile("ldmatrix.sync.aligned.m8n8.x4.trans.shared.b16 {%0,%1,%2,%3}, [%4];"
        : "=r"(r[0]), "=r"(r[1]), "=r"(r[2]), "=r"(r[3]) : "r"(a));
}

struct GemmCfgH {
    void* out[4];
    const float* bias[4];
    int act[4];
};

// ---------------------------------------------------------------------------
// fp16 GEMM: A via cp.async+ldmatrix (KTH=64, 16 barriers); B fragments via
// LDG.64 from packed weights (register double-buffered). 8 warps (2x4).
// ---------------------------------------------------------------------------
template<int HOUT>
__global__ __launch_bounds__(256) void gemm_h(
    const __half* __restrict__ A, const uint2* __restrict__ Bp, GemmCfgH cfg)
{
    extern __shared__ __align__(16) __half gsm[];
    const int t = threadIdx.x;
    const int wid = t >> 5, lane = t & 31;
    const int wm = wid >> 2, wn = wid & 3;
    const int m0 = blockIdx.y * 128, n0 = blockIdx.x * 128;
    const int bsel = n0 >> 10;
    const int ncol0 = n0 & 1023;
    const int lq = lane >> 2, lr = lane & 3;

    const uint32_t sA0 = smem_u32(gsm);
    const uint32_t bufStride = GBUF * 2;  // bytes per A stage

    const int l15 = lane & 15;
    const int k8a = (lane & 16) ? 8 : 0;
    const uint32_t aoff = ((wm * 64 + l15) * SH + k8a) * 2;

    const int n8base = (n0 + wn * 32) >> 3;
    const uint2* bb = Bp + (size_t)n8base * (64 * 32) + lane;

    float acc[4][4][4];
    #pragma unroll
    for (int i = 0; i < 4; i++)
        #pragma unroll
        for (int j = 0; j < 4; j++)
            #pragma unroll
            for (int q = 0; q < 4; q++) acc[i][j][q] = 0.f;

    auto loadTile = [&](int kt, int buf) {
        const int k0 = kt * KTH;
        #pragma unroll
        for (int i = 0; i < 4; i++) {
            int s = t + i * 256;
            int row = s >> 3, seg = s & 7;
            cpa16(sA0 + buf * bufStride + (row * SH + seg * 8) * 2,
                  A + (size_t)(m0 + row) * DM + k0 + seg * 8);
        }
        asm volatile("cp.async.commit_group;" ::: "memory");
    };

    // B fragment register double-buffer
    uint2 breg[2][4];
    #pragma unroll
    for (int j = 0; j < 4; j++) breg[0][j] = bb[(size_t)j * (64 * 32)];

    loadTile(0, 0);

    for (int kt = 0; kt < NKTH; kt++) {
        if (kt + 1 < NKTH) {
            loadTile(kt + 1, (kt + 1) & 1);
            asm volatile("cp.async.wait_group 1;" ::: "memory");
        } else {
            asm volatile("cp.async.wait_group 0;" ::: "memory");
        }
        __syncthreads();

        const uint32_t aB = sA0 + (kt & 1) * bufStride;

        #pragma unroll
        for (int ks = 0; ks < 4; ks++) {          // 4 k16 steps per KTH=64
            const int kk = kt * 4 + ks;
            if (kk + 1 < NKK) {
                #pragma unroll
                for (int j = 0; j < 4; j++)
                    breg[(kk + 1) & 1][j] = bb[(size_t)j * (64 * 32) + (kk + 1) * 32];
            }
            uint32_t af[4][4];
            #pragma unroll
            for (int mi = 0; mi < 4; mi++)
                ldsm_x4(af[mi], aB + aoff + mi * (16 * SH * 2) + ks * 32);
            const uint2* bc = breg[kk & 1];
            #pragma unroll
            for (int mi = 0; mi < 4; mi++) {
                #pragma unroll
                for (int ni = 0; ni < 4; ni++) {
                    uint32_t bf[2] = { bc[ni].x, bc[ni].y };
                    mma_f16(acc[mi][ni], af[mi], bf);
                }
            }
        }
        __syncthreads();
    }

    const float* bp = cfg.bias[bsel];
    const int act = cfg.act[bsel];

    #pragma unroll
    for (int mi = 0; mi < 4; mi++) {
        #pragma unroll
        for (int ni = 0; ni < 4; ni++) {
            const int col = ncol0 + wn * 32 + ni * 8 + lr * 2;
            float b0 = 0.f, b1 = 0.f;
            if (bp) { b0 = bp[col]; b1 = bp[col + 1]; }
            #pragma unroll
            for (int h = 0; h < 2; h++) {
                const int row = m0 + wm * 64 + mi * 16 + lq + h * 8;
                float z0 = acc[mi][ni][h * 2 + 0] + b0;
                float z1 = acc[mi][ni][h * 2 + 1] + b1;
                if (act) {
                    z0 = z0 / (1.0f + expf(-z0));
                    z1 = z1 / (1.0f + expf(-z1));
                }
                if (HOUT) {
                    *(__half2*)((__half*)cfg.out[bsel] + (size_t)row * DM + col) =
                        __floats2half2_rn(z0, z1);
                } else {
                    float2 v = make_float2(z0, z1);
                    *(float2*)((float*)cfg.out[bsel] + (size_t)row * DM + col) = v;
                }
            }
        }
    }
}

// ---------------------------------------------------------------------------
// Prep: X f32 -> half; 5 weights -> fragment-packed half
// ---------------------------------------------------------------------------
__global__ __launch_bounds__(256) void cvt_x(const float* __restrict__ in,
                                             __half* __restrict__ out)
{
    size_t i = ((size_t)blockIdx.x * 256 + threadIdx.x) * 8;
    float4 v0 = *(const float4*)(in + i);
    float4 v1 = *(const float4*)(in + i + 4);
    uint32_t o[4];
    o[0] = h2_u32(__floats2half2_rn(v0.x, v0.y));
    o[1] = h2_u32(__floats2half2_rn(v0.z, v0.w));
    o[2] = h2_u32(__floats2half2_rn(v1.x, v1.y));
    o[3] = h2_u32(__floats2half2_rn(v1.z, v1.w));
    *(uint4*)(out + i) = make_uint4(o[0], o[1], o[2], o[3]);
}

__global__ __launch_bounds__(256) void transpose_pack5(
    const float* Wq, const float* Wk, const float* Wv, const float* Wg,
    const float* Wo, uint2* Bp4, uint2* BpO)
{
    __shared__ float tile[32][33];
    const int z = blockIdx.z;
    const float* W = (z == 0) ? Wq : (z == 1) ? Wk : (z == 2) ? Wv : (z == 3) ? Wg : Wo;
    const int k0 = blockIdx.x * 32, n0 = blockIdx.y * 32;
    const int tx = threadIdx.x & 31, ty = threadIdx.x >> 5;
    #pragma unroll
    for (int i = 0; i < 32; i += 8)
        tile[ty + i][tx] = W[(size_t)(k0 + ty + i) * DM + n0 + tx];
    __syncthreads();

    const int w = threadIdx.x >> 5, l = threadIdx.x & 31;
    const int kkl = w >> 2, jl = w & 3;
    const int nl = jl * 8 + (l >> 2);
    const int kl = kkl * 16 + 2 * (l & 3);
    uint32_t b0 = h2_u32(__floats2half2_rn(tile[kl][nl],     tile[kl + 1][nl]));
    uint32_t b1 = h2_u32(__floats2half2_rn(tile[kl + 8][nl], tile[kl + 9][nl]));
    const int kkg = (k0 >> 4) + kkl;
    if (z < 4) {
        size_t jg = (size_t)z * 128 + (n0 >> 3) + jl;
        Bp4[(jg * 64 + kkg) * 32 + l] = make_uint2(b0, b1);
    } else {
        size_t jg = (size_t)(n0 >> 3) + jl;
        BpO[(jg * 64 + kkg) * 32 + l] = make_uint2(b0, b1);
    }
}

// ---------------------------------------------------------------------------
// Retention fp16: S in registers (C-frag == A-frag), split-k over tokens,
// cross-warp reduction at the end. (diag-skip reverted — it cost 5.6 us)
// ---------------------------------------------------------------------------
__global__ __launch_bounds__(256, 3) void retention_h(
    const __half* __restrict__ Q, const __half* __restrict__ K,
    const __half* __restrict__ V, float* __restrict__ R)
{
    extern __shared__ __align__(16) __half rsm[];
    const uint32_t sQ = smem_u32(rsm);
    const uint32_t sK = sQ + RBUF * 2;
    const uint32_t sV = sK + 2 * RBUF * 2;

    const int idx = blockIdx.x;
    const int qb = (TT/64 - 1) - (idx >> 5);
    const int rem = idx & 31;
    const int h = 15 - (rem >> 1);
    const int b = rem & 1;

    const int t = threadIdx.x;
    const int wid = t >> 5, lane = t & 31;
    const int wm = wid >> 1, wn = wid & 1;
    const int lq = lane >> 2, lr = lane & 3;
    const size_t base = (size_t)b * TT * DM + (size_t)h * DH;
    const int t0 = qb * 64;

    const int l15 = lane & 15;
    const int k8a = (lane & 16) ? 8 : 0;
    const uint32_t qoff  = ((wm * 16 + l15) * RST + k8a) * 2;
    const uint32_t koffB = ((wn * 32 + (lane & 7) + k8a) * RST + ((lane & 8) ? 8 : 0)) * 2;
    const uint32_t voffB = (l15 * RST + k8a) * 2;

    #pragma unroll
    for (int i = 0; i < 2; i++) {
        int s = t + i * 256;
        int row = s >> 3, seg = s & 7;
        cpa16(sQ + (row * RST + seg * 8) * 2,
              Q + base + (size_t)(t0 + row) * DM + seg * 8);
    }
    asm volatile("cp.async.commit_group;" ::: "memory");

    const float gamma = 1.0f - exp2f(-(float)(5 + h));
    const float l2g   = log2f(gamma);
    float diffmax = 24.0f / (-l2g);
    int nb_back = (diffmax > 1.0e8f) ? qb : ((int)(diffmax * (1.0f / 64.0f)) + 2);
    int sb0 = qb - nb_back; if (sb0 < 0) sb0 = 0;
    const int nit = qb - sb0 + 1;

    float rowf[2], colf[8];
    #pragma unroll
    for (int i = 0; i < 2; i++)
        rowf[i] = exp2f(l2g * (float)(wm * 16 + lq + 8 * i)) * 0.125f;
    #pragma unroll
    for (int ni = 0; ni < 4; ni++)
        #pragma unroll
        for (int j = 0; j < 2; j++)
            colf[ni * 2 + j] = exp2f(-l2g * (float)(wn * 32 + ni * 8 + 2 * lr + j));

    auto loadKV = [&](int sb, int buf) {
        #pragma unroll
        for (int i = 0; i < 2; i++) {
            int s = t + i * 256;
            int row = s >> 3, seg = s & 7;
            cpa16(sK + (buf * RBUF + row * RST + seg * 8) * 2,
                  K + base + (size_t)(sb * 64 + row) * DM + seg * 8);
            cpa16(sV + (buf * RBUF + row * RST + seg * 8) * 2,
                  V + base + (size_t)(sb * 64 + row) * DM + seg * 8);
        }
        asm volatile("cp.async.commit_group;" ::: "memory");
    };

    loadKV(sb0, 0);

    float oacc[8][4];
    #pragma unroll
    for (int nj = 0; nj < 8; nj++)
        #pragma unroll
        for (int q = 0; q < 4; q++) oacc[nj][q] = 0.f;

    for (int it = 0; it < nit; it++) {
        const int sb = sb0 + it;
        const int buf = it & 1;
        asm volatile("cp.async.wait_group 0;" ::: "memory");
        __syncthreads();

        // ---- S = Q K^T ----
        float sacc[4][4];
        #pragma unroll
        for (int ni = 0; ni < 4; ni++)
            #pragma unroll
            for (int q = 0; q < 4; q++) sacc[ni][q] = 0.f;

        const uint32_t kB = sK + buf * RBUF * 2;
        #pragma unroll
        for (int ks = 0; ks < 4; ks++) {
            const uint32_t kb = ks * 32;
            uint32_t af[4], b01[4], b23[4];
            ldsm_x4(af, sQ + qoff + kb);
            ldsm_x4(b01, kB + koffB + kb);
            ldsm_x4(b23, kB + koffB + 16 * RST * 2 + kb);
            mma_f16(sacc[0], af, b01 + 0);
            mma_f16(sacc[1], af, b01 + 2);
            mma_f16(sacc[2], af, b23 + 0);
            mma_f16(sacc[3], af, b23 + 2);
        }

        if (it + 1 < nit) loadKV(sb + 1, (it + 1) & 1);
        else asm volatile("cp.async.commit_group;" ::: "memory");

        // ---- decay + causal in regs; pack C-frags as A-frags ----
        const float pb = exp2f(l2g * (float)(64 * (qb - sb)));
        const bool diag = (sb == qb);
        uint32_t afr[2][4];
        #pragma unroll
        for (int ni = 0; ni < 4; ni++) {
            const int nl0 = wn * 32 + ni * 8 + 2 * lr;
            const float wr0 = rowf[0] * pb;
            const float wr1 = rowf[1] * pb;
            const int m0r = wm * 16 + lq;
            float v0 = sacc[ni][0] * (wr0 * colf[ni * 2 + 0]);
            float v1 = sacc[ni][1] * (wr0 * colf[ni * 2 + 1]);
            float v2 = sacc[ni][2] * (wr1 * colf[ni * 2 + 0]);
            float v3 = sacc[ni][3] * (wr1 * colf[ni * 2 + 1]);
            if (diag && nl0     > m0r)     v0 = 0.f;
            if (diag && nl0 + 1 > m0r)     v1 = 0.f;
            if (diag && nl0     > m0r + 8) v2 = 0.f;
            if (diag && nl0 + 1 > m0r + 8) v3 = 0.f;
            afr[ni >> 1][(ni & 1) * 2 + 0] = h2_u32(__floats2half2_rn(v0, v1));
            afr[ni >> 1][(ni & 1) * 2 + 1] = h2_u32(__floats2half2_rn(v2, v3));
        }

        // ---- O partial += S V ----
        const uint32_t vB = sV + buf * RBUF * 2;
        #pragma unroll
        for (int kb = 0; kb < 2; kb++) {
            const uint32_t rowb = (uint32_t)((wn * 32 + kb * 16) * RST) * 2;
            #pragma unroll
            for (int nj4 = 0; nj4 < 4; nj4++) {
                uint32_t bq[4];
                ldsm_x4t(bq, vB + voffB + rowb + nj4 * 32);
                mma_f16(oacc[nj4 * 2 + 0], afr[kb], bq + 0);
                mma_f16(oacc[nj4 * 2 + 1], afr[kb], bq + 2);
            }
        }
    }

    // cross-warp (wn) reduction, then write R
    __syncthreads();
    float* red = (float*)rsm;
    const int RRST = 66;
    if (wn == 1) {
        #pragma unroll
        for (int nj = 0; nj < 8; nj++)
            #pragma unroll
            for (int h_ = 0; h_ < 2; h_++) {
                const int r = wm * 16 + lq + 8 * h_;
                float2 v = make_float2(oacc[nj][h_ * 2 + 0], oacc[nj][h_ * 2 + 1]);
                *(float2*)&red[r * RRST + nj * 8 + 2 * lr] = v;
            }
    }
    __syncthreads();
    if (wn == 0) {
        #pragma unroll
        for (int nj = 0; nj < 8; nj++)
            #pragma unroll
            for (int h_ = 0; h_ < 2; h_++) {
                const int r = wm * 16 + lq + 8 * h_;
                const int col = nj * 8 + 2 * lr;
                float2 p = *(float2*)&red[r * RRST + col];
                float2 v = make_float2(oacc[nj][h_ * 2 + 0] + p.x,
                                       oacc[nj][h_ * 2 + 1] + p.y);
                *(float2*)(R + base + (size_t)(t0 + r) * DM + col) = v;
            }
    }
}

// ---------------------------------------------------------------------------
// LayerNorm * gate: R f32, G half -> Y half
// ---------------------------------------------------------------------------
__global__ __launch_bounds__(256) void ln_gate_h(
    const float* __restrict__ R, const __half* __restrict__ G,
    const float* __restrict__ lng, const float* __restrict__ lnb,
    __half* __restrict__ Y)
{
    __shared__ float red[8];
    const int row = blockIdx.x;
    const int t = threadIdx.x;
    const size_t off = (size_t)row * DM + t * 4;

    float4 x = *(const float4*)(R + off);

    float s = x.x + x.y + x.z + x.w;
    #pragma unroll
    for (int o = 16; o > 0; o >>= 1) s += __shfl_xor_sync(0xffffffffu, s, o);
    if ((t & 31) == 0) red[t >> 5] = s;
    __syncthreads();
    float tot = red[0] + red[1] + red[2] + red[3] + red[4] + red[5] + red[6] + red[7];
    const float mu = tot * (1.0f / 1024.0f);

    float d0 = x.x - mu, d1 = x.y - mu, d2 = x.z - mu, d3 = x.w - mu;
    float sq = d0 * d0 + d1 * d1 + d2 * d2 + d3 * d3;
    #pragma unroll
    for (int o = 16; o > 0; o >>= 1) sq += __shfl_xor_sync(0xffffffffu, sq, o);
    __syncthreads();
    if ((t & 31) == 0) red[t >> 5] = sq;
    __syncthreads();
    float totsq = red[0] + red[1] + red[2] + red[3] + red[4] + red[5] + red[6] + red[7];
    const float rstd = rsqrtf(totsq * (1.0f / 1024.0f) + 1e-3f);

    float4 g4 = *(const float4*)(lng + t * 4);
    float4 b4 = *(const float4*)(lnb + t * 4);
    uint2 gu = *(const uint2*)(G + off);
    float2 ga = __half22float2(*(__half2*)&gu.x);
    float2 gb = __half22float2(*(__half2*)&gu.y);

    __half2 y0 = __floats2half2_rn((d0 * rstd * g4.x + b4.x) * ga.x,
                                   (d1 * rstd * g4.y + b4.y) * ga.y);
    __half2 y1 = __floats2half2_rn((d2 * rstd * g4.z + b4.z) * gb.x,
                                   (d3 * rstd * g4.w + b4.w) * gb.y);
    __half2* yp = (__half2*)(Y + off);
    yp[0] = y0;
    yp[1] = y1;
}

// ---------------------------------------------------------------------------
extern "C" void kernel_launch(void* const* d_in, const int* in_sizes, int n_in,
                              void* d_out, int out_size)
{
    const float* x   = (const float*)d_in[0];
    const float* Wq  = (const float*)d_in[1];
    const float* Wk  = (const float*)d_in[2];
    const float* Wv  = (const float*)d_in[3];
    const float* Wg  = (const float*)d_in[4];
    const float* bg  = (const float*)d_in[5];
    const float* Wo  = (const float*)d_in[6];
    const float* bo  = (const float*)d_in[7];
    const float* lng = (const float*)d_in[8];
    const float* lnb = (const float*)d_in[9];

    __half *Qh, *Kh, *Vh, *Gh, *Xh, *Yh;
    uint2 *Bp4, *BpO;
    float *R;
    cudaGetSymbolAddress((void**)&Qh,  g_Qh);
    cudaGetSymbolAddress((void**)&Kh,  g_Kh);
    cudaGetSymbolAddress((void**)&Vh,  g_Vh);
    cudaGetSymbolAddress((void**)&Gh,  g_Gh);
    cudaGetSymbolAddress((void**)&Xh,  g_Xh);
    cudaGetSymbolAddress((void**)&Yh,  g_Yh);
    cudaGetSymbolAddress((void**)&Bp4, g_Bp4);
    cudaGetSymbolAddress((void**)&BpO, g_BpO);
    cudaGetSymbolAddress((void**)&R,   g_R);

    cvt_x<<<(NTOK * DM) / (256 * 8), 256>>>(x, Xh);
    transpose_pack5<<<dim3(32, 32, 5), 256>>>(Wq, Wk, Wv, Wg, Wo, Bp4, BpO);

    GemmCfgH c1;
    c1.out[0] = Qh; c1.out[1] = Kh; c1.out[2] = Vh; c1.out[3] = Gh;
    c1.bias[0] = nullptr; c1.bias[1] = nullptr; c1.bias[2] = nullptr; c1.bias[3] = bg;
    c1.act[0] = 0; c1.act[1] = 0; c1.act[2] = 0; c1.act[3] = 1;
    gemm_h<1><<<dim3(32, 32), 256, GEMM_SMEM>>>(Xh, Bp4, c1);

    cudaFuncSetAttribute(retention_h, cudaFuncAttributeMaxDynamicSharedMemorySize, RET_SMEM);
    retention_h<<<dim3((TT/64) * NH * BB), 256, RET_SMEM>>>(Qh, Kh, Vh, R);

    ln_gate_h<<<NTOK, 256>>>(R, Gh, lng, lnb, Yh);

    GemmCfgH c2;
    c2.out[0] = d_out; c2.out[1] = nullptr; c2.out[2] = nullptr; c2.out[3] = nullptr;
    c2.bias[0] = bo; c2.bias[1] = nullptr; c2.bias[2] = nullptr; c2.bias[3] = nullptr;
    c2.act[0] = 0; c2.act[1] = 0; c2.act[2] = 0; c2.act[3] = 0;
    gemm_h<0><<<dim3(8, 32), 256, GEMM_SMEM>>>(Yh, BpO, c2);
}